// round 11
// baseline (speedup 1.0000x reference)
#include <cuda_runtime.h>
#include <cuda_fp16.h>
#include <math.h>
#include <stdint.h>

#define MROWS 2048
#define EMB   512

// ---------------- scratch (device globals) -----------------------------------
__device__ float  g_T1 [4UL*2048*512];
__device__ float  g_R1 [4UL*2048*512];
__device__ float  g_T2 [4UL*2048*512];
__device__ __half g_Xh [4UL*2048*512];
__device__ __half g_Q  [4UL*2048*512];   // [s,b,h,t,d]
__device__ __half g_K  [4UL*2048*512];
__device__ __half g_V  [4UL*2048*512];
__device__ __half g_MH [4UL*2048*512];   // pre-transposed attention out
__device__ __half g_R1h[4UL*2048*512];
__device__ __half g_HB [4UL*2048*2048];
__device__ __half g_Wqh[4UL*512*512];
__device__ __half g_Wkh[4UL*512*512];
__device__ __half g_Wvh[4UL*512*512];
__device__ __half g_Woh[4UL*512*512];
__device__ __half g_W1h[4UL*512*2048];
__device__ __half g_W2h[4UL*2048*512];

struct R4 { const float* p[4]; };
struct CvtDesc {
    const float* src[10];
    __half* dst[10];
    int start[11];
};

__device__ __forceinline__ float gelu_exact(float x) {
    return 0.5f * x * (1.0f + erff(x * 0.70710678118654752440f));
}
__device__ __forceinline__ uint32_t sptr(const void* p) {
    return (uint32_t)__cvta_generic_to_shared(p);
}
__device__ __forceinline__ void cpa16(void* s, const void* g) {
    asm volatile("cp.async.cg.shared.global [%0],[%1],16;\n" :: "r"(sptr(s)), "l"(g));
}
__device__ __forceinline__ void ldsm4(uint32_t& r0, uint32_t& r1, uint32_t& r2,
                                      uint32_t& r3, uint32_t a) {
    asm volatile("ldmatrix.sync.aligned.m8n8.x4.shared.b16 {%0,%1,%2,%3},[%4];\n"
        : "=r"(r0), "=r"(r1), "=r"(r2), "=r"(r3) : "r"(a));
}
__device__ __forceinline__ void ldsm4t(uint32_t& r0, uint32_t& r1, uint32_t& r2,
                                       uint32_t& r3, uint32_t a) {
    asm volatile("ldmatrix.sync.aligned.m8n8.x4.trans.shared.b16 {%0,%1,%2,%3},[%4];\n"
        : "=r"(r0), "=r"(r1), "=r"(r2), "=r"(r3) : "r"(a));
}
__device__ __forceinline__ void mmaf16(float& d0, float& d1, float& d2, float& d3,
    uint32_t a0, uint32_t a1, uint32_t a2, uint32_t a3, uint32_t b0, uint32_t b1) {
    asm volatile("mma.sync.aligned.m16n8k16.row.col.f32.f16.f16.f32 "
        "{%0,%1,%2,%3},{%4,%5,%6,%7},{%8,%9},{%0,%1,%2,%3};\n"
        : "+f"(d0), "+f"(d1), "+f"(d2), "+f"(d3)
        : "r"(a0), "r"(a1), "r"(a2), "r"(a3), "r"(b0), "r"(b1));
}
__device__ __forceinline__ uint32_t packh2(float x, float y) {
    __half2 h = __floats2half2_rn(x, y);
    return *(uint32_t*)&h;
}
__device__ __forceinline__ float ex2f(float x) {
    float y; asm("ex2.approx.f32 %0, %1;" : "=f"(y) : "f"(x)); return y;
}

// ---------------- single fused fp32->fp16 converter ----------------------------
__global__ __launch_bounds__(256)
void cvt_all(CvtDesc d)
{
    int b = blockIdx.x;
    int seg = 0;
    #pragma unroll
    for (int k = 0; k < 9; ++k)
        if (b >= d.start[seg + 1]) ++seg;
    int off = (b - d.start[seg]) * 1024 + threadIdx.x * 4;
    float4 v = *(const float4*)(d.src[seg] + off);
    __half* o = d.dst[seg] + off;
    *(__half2*)(o)     = __floats2half2_rn(v.x, v.y);
    *(__half2*)(o + 2) = __floats2half2_rn(v.z, v.w);
}

// ---------------- fp16 MMA GEMM core: 128x128x32, 256 thr, 2-stage -------------
#define LDA 40
#define LDB 152
#define AS_SZ (128*LDA)
#define BS_SZ (32*LDB)

__device__ __forceinline__ void stage_h(const __half* Ag, const __half* Bg,
    int K, int N, __half* Ad, __half* Bd, int tid)
{
    #pragma unroll
    for (int i = 0; i < 2; ++i) {
        int c = tid + (i << 8);
        int ar = c >> 2, ac = (c & 3) << 3;
        cpa16(Ad + ar * LDA + ac, Ag + (size_t)ar * K + ac);
        int br = c >> 4, bn = (c & 15) << 3;
        cpa16(Bd + br * LDB + bn, Bg + (size_t)br * N + bn);
    }
    asm volatile("cp.async.commit_group;\n" ::: "memory");
}

__device__ __forceinline__ void mainloop_h(
    const __half* __restrict__ A, const __half* __restrict__ B,
    int K, int N, int m0, int n0, float (&acc)[4][4][4],
    __half* As, __half* Bs)
{
    const int tid = threadIdx.x, lane = tid & 31, warp = tid >> 5;
    const int wm = (warp & 1) * 64, wn = (warp >> 1) * 32;
    const int KT = K >> 5;
    const int lrow = lane & 15, lsel = (lane >> 4) << 3;

    stage_h(A + (size_t)m0 * K, B + n0, K, N, As, Bs, tid);

    for (int kt = 0; kt < KT; ++kt) {
        int buf = kt & 1;
        if (kt + 1 < KT) {
            stage_h(A + (size_t)m0 * K + (kt + 1) * 32,
                    B + (size_t)(kt + 1) * 32 * N + n0, K, N,
                    As + (buf ^ 1) * AS_SZ, Bs + (buf ^ 1) * BS_SZ, tid);
            asm volatile("cp.async.wait_group 1;\n" ::: "memory");
        } else {
            asm volatile("cp.async.wait_group 0;\n" ::: "memory");
        }
        __syncthreads();
        const __half* Ad = As + buf * AS_SZ;
        const __half* Bd = Bs + buf * BS_SZ;
        #pragma unroll
        for (int kk = 0; kk < 2; ++kk) {
            int kb = kk * 16;
            uint32_t af[4][4], bf[2][4];
            #pragma unroll
            for (int mi = 0; mi < 4; ++mi)
                ldsm4(af[mi][0], af[mi][1], af[mi][2], af[mi][3],
                      sptr(Ad + (wm + mi * 16 + lrow) * LDA + kb + lsel));
            #pragma unroll
            for (int p = 0; p < 2; ++p)
                ldsm4t(bf[p][0], bf[p][1], bf[p][2], bf[p][3],
                       sptr(Bd + (kb + lrow) * LDB + wn + p * 16 + lsel));
            #pragma unroll
            for (int mi = 0; mi < 4; ++mi)
                #pragma unroll
                for (int ni = 0; ni < 4; ++ni)
                    mmaf16(acc[mi][ni][0], acc[mi][ni][1], acc[mi][ni][2], acc[mi][ni][3],
                           af[mi][0], af[mi][1], af[mi][2], af[mi][3],
                           bf[ni >> 1][(ni & 1) * 2], bf[ni >> 1][(ni & 1) * 2 + 1]);
        }
        __syncthreads();
    }
}

// ---------------- 64x128 variant (for latency-bound N=512 GEMMs) ---------------
#define AS64 (64*LDA)

__device__ __forceinline__ void stage_h64(const __half* Ag, const __half* Bg,
    int K, int N, __half* Ad, __half* Bd, int tid)
{
    {
        int ar = tid >> 2, ac = (tid & 3) << 3;
        cpa16(Ad + ar * LDA + ac, Ag + (size_t)ar * K + ac);
    }
    #pragma unroll
    for (int i = 0; i < 2; ++i) {
        int c = tid + (i << 8);
        int br = c >> 4, bn = (c & 15) << 3;
        cpa16(Bd + br * LDB + bn, Bg + (size_t)br * N + bn);
    }
    asm volatile("cp.async.commit_group;\n" ::: "memory");
}

__device__ __forceinline__ void mainloop_h64(
    const __half* __restrict__ A, const __half* __restrict__ B,
    int K, int N, int m0, int n0, float (&acc)[2][4][4],
    __half* As, __half* Bs)
{
    const int tid = threadIdx.x, lane = tid & 31, warp = tid >> 5;
    const int wm = (warp & 1) * 32, wn = (warp >> 1) * 32;
    const int KT = K >> 5;
    const int lrow = lane & 15, lsel = (lane >> 4) << 3;

    stage_h64(A + (size_t)m0 * K, B + n0, K, N, As, Bs, tid);

    for (int kt = 0; kt < KT; ++kt) {
        int buf = kt & 1;
        if (kt + 1 < KT) {
            stage_h64(A + (size_t)m0 * K + (kt + 1) * 32,
                      B + (size_t)(kt + 1) * 32 * N + n0, K, N,
                      As + (buf ^ 1) * AS64, Bs + (buf ^ 1) * BS_SZ, tid);
            asm volatile("cp.async.wait_group 1;\n" ::: "memory");
        } else {
            asm volatile("cp.async.wait_group 0;\n" ::: "memory");
        }
        __syncthreads();
        const __half* Ad = As + buf * AS64;
        const __half* Bd = Bs + buf * BS_SZ;
        #pragma unroll
        for (int kk = 0; kk < 2; ++kk) {
            int kb = kk * 16;
            uint32_t af[2][4], bf[2][4];
            #pragma unroll
            for (int mi = 0; mi < 2; ++mi)
                ldsm4(af[mi][0], af[mi][1], af[mi][2], af[mi][3],
                      sptr(Ad + (wm + mi * 16 + lrow) * LDA + kb + lsel));
            #pragma unroll
            for (int p = 0; p < 2; ++p)
                ldsm4t(bf[p][0], bf[p][1], bf[p][2], bf[p][3],
                       sptr(Bd + (kb + lrow) * LDB + wn + p * 16 + lsel));
            #pragma unroll
            for (int mi = 0; mi < 2; ++mi)
                #pragma unroll
                for (int ni = 0; ni < 4; ++ni)
                    mmaf16(acc[mi][ni][0], acc[mi][ni][1], acc[mi][ni][2], acc[mi][ni][3],
                           af[mi][0], af[mi][1], af[mi][2], af[mi][3],
                           bf[ni >> 1][(ni & 1) * 2], bf[ni >> 1][(ni & 1) * 2 + 1]);
        }
        __syncthreads();
    }
}

// ---------------- QKV: Xh @ W -> scatter half [s,b,h,t,d] --------------------
__global__ __launch_bounds__(256)
void qkv_mma()
{
    __shared__ __half As[2 * AS_SZ];
    __shared__ __half Bs[2 * BS_SZ];
    int z = blockIdx.z; int s = z / 3, p = z - 3 * s;
    const __half* A = g_Xh + (size_t)s * MROWS * EMB;
    const __half* W = (p == 0 ? g_Wqh : (p == 1 ? g_Wkh : g_Wvh)) + (size_t)s * EMB * EMB;
    __half* O = (p == 0 ? g_Q : (p == 1 ? g_K : g_V));
    int m0 = blockIdx.y * 128, n0 = blockIdx.x * 128;

    float acc[4][4][4] = {};
    mainloop_h(A, W, EMB, EMB, m0, n0, acc, As, Bs);

    const int lane = threadIdx.x & 31, warp = threadIdx.x >> 5;
    const int wm = (warp & 1) * 64, wn = (warp >> 1) * 32;
    const int gg = lane >> 2, rr = lane & 3;
    #pragma unroll
    for (int mi = 0; mi < 4; ++mi) {
        int r0 = m0 + wm + mi * 16 + gg;
        #pragma unroll
        for (int ni = 0; ni < 4; ++ni) {
            int c = n0 + wn + ni * 8 + rr * 2;
            int hh = c >> 6, d = c & 63;
            #pragma unroll
            for (int hr = 0; hr < 2; ++hr) {
                int rw = r0 + hr * 8;
                int b = rw >> 9, t = rw & 511;
                size_t dst = ((((size_t)s * 4 + b) * 8 + hh) * 512 + t) * 64 + d;
                __half2 hv = __floats2half2_rn(acc[mi][ni][hr * 2], acc[mi][ni][hr * 2 + 1]);
                *(__half2*)(O + dst) = hv;
            }
        }
    }
}

// ---------------- 64-tile GEMM + bias + resid -> fp32 (Wo, FFN2) ---------------
__global__ __launch_bounds__(256)
void gemm_bias_resid64(const __half* __restrict__ Ab, const __half* __restrict__ Bb,
                       const float* __restrict__ biasb, R4 resid,
                       float* __restrict__ Cb, int M, int N, int K)
{
    __shared__ __half As[2 * AS64];
    __shared__ __half Bs[2 * BS_SZ];
    int s = blockIdx.z;
    const __half* A = Ab + (size_t)s * M * K;
    const __half* B = Bb + (size_t)s * K * N;
    const float* bias = biasb + (size_t)s * N;
    const float* R = resid.p[s];
    float* C = Cb + (size_t)s * M * N;
    int m0 = blockIdx.y * 64, n0 = blockIdx.x * 128;

    float acc[2][4][4] = {};
    mainloop_h64(A, B, K, N, m0, n0, acc, As, Bs);

    const int lane = threadIdx.x & 31, warp = threadIdx.x >> 5;
    const int wm = (warp & 1) * 32, wn = (warp >> 1) * 32;
    const int gg = lane >> 2, rr = lane & 3;
    #pragma unroll
    for (int mi = 0; mi < 2; ++mi) {
        int r0 = m0 + wm + mi * 16 + gg;
        #pragma unroll
        for (int ni = 0; ni < 4; ++ni) {
            int c = n0 + wn + ni * 8 + rr * 2;
            float bx = bias[c], by = bias[c + 1];
            #pragma unroll
            for (int hr = 0; hr < 2; ++hr) {
                int rw = r0 + hr * 8;
                float2 rv = *(const float2*)(R + (size_t)rw * N + c);
                float v0 = acc[mi][ni][hr * 2 + 0] + bx + rv.x;
                float v1 = acc[mi][ni][hr * 2 + 1] + by + rv.y;
                *(float2*)(C + (size_t)rw * N + c) = make_float2(v0, v1);
            }
        }
    }
}

// ---------------- GEMM + bias + gelu -> fp16 (FFN1) ----------------------------
__global__ __launch_bounds__(256)
void gemm_bias_gelu(const __half* __restrict__ Ab, const __half* __restrict__ Bb,
                    const float* __restrict__ biasb, __half* __restrict__ Cb,
                    int M, int N, int K)
{
    __shared__ __half As[2 * AS_SZ];
    __shared__ __half Bs[2 * BS_SZ];
    int s = blockIdx.z;
    const __half* A = Ab + (size_t)s * M * K;
    const __half* B = Bb + (size_t)s * K * N;
    const float* bias = biasb + (size_t)s * N;
    __half* C = Cb + (size_t)s * M * N;
    int m0 = blockIdx.y * 128, n0 = blockIdx.x * 128;

    float acc[4][4][4] = {};
    mainloop_h(A, B, K, N, m0, n0, acc, As, Bs);

    const int lane = threadIdx.x & 31, warp = threadIdx.x >> 5;
    const int wm = (warp & 1) * 64, wn = (warp >> 1) * 32;
    const int gg = lane >> 2, rr = lane & 3;
    #pragma unroll
    for (int mi = 0; mi < 4; ++mi) {
        int r0 = m0 + wm + mi * 16 + gg;
        #pragma unroll
        for (int ni = 0; ni < 4; ++ni) {
            int c = n0 + wn + ni * 8 + rr * 2;
            float bx = bias[c], by = bias[c + 1];
            #pragma unroll
            for (int hr = 0; hr < 2; ++hr) {
                int rw = r0 + hr * 8;
                float v0 = gelu_exact(acc[mi][ni][hr * 2 + 0] + bx);
                float v1 = gelu_exact(acc[mi][ni][hr * 2 + 1] + by);
                *(__half2*)(C + (size_t)rw * N + c) = __floats2half2_rn(v0, v1);
            }
        }
    }
}

// ---------------- cross-stream flash attention (serial KV, no-max softmax) -----
__global__ __launch_bounds__(128)
void attn_h(const float* __restrict__ inter)
{
    __shared__ __half Qs[64 * 72];
    __shared__ __half Ks[64 * 72];
    __shared__ __half Vs[64 * 72];

    const int tid = threadIdx.x, lane = tid & 31, warp = tid >> 5;
    const int qt = blockIdx.x, h = blockIdx.y, ib = blockIdx.z;
    const int i = ib >> 2, b = ib & 3;
    const int gg = lane >> 2, rr = lane & 3;
    const int lrow = lane & 15, lsel = (lane >> 4) << 3;

    const __half* Qg = g_Q + ((((size_t)i * 4 + b) * 8 + h) * 512 + qt * 64) * 64;
    #pragma unroll
    for (int it = 0; it < 4; ++it) {
        int c = tid + it * 128;
        int q = c >> 3, d8 = (c & 7) << 3;
        cpa16(Qs + q * 72 + d8, Qg + q * 64 + d8);
    }
    asm volatile("cp.async.commit_group;\ncp.async.wait_group 0;\n" ::: "memory");
    __syncthreads();

    uint32_t qf[4][4];
    #pragma unroll
    for (int kf = 0; kf < 4; ++kf)
        ldsm4(qf[kf][0], qf[kf][1], qf[kf][2], qf[kf][3],
              sptr(Qs + (warp * 16 + lrow) * 72 + kf * 16 + lsel));

    float Of[8][4] = {};
    for (int j = 0; j < 4; ++j) {
        float cj2 = 0.125f * 1.44269504f * __ldg(inter + i * 4 + j);
        const __half* Kg = g_K + (((size_t)j * 4 + b) * 8 + h) * 512 * 64;
        const __half* Vg = g_V + (((size_t)j * 4 + b) * 8 + h) * 512 * 64;
        float l0 = 0.f, l1 = 0.f;
        float Oj[8][4] = {};

        for (int kt = 0; kt < 8; ++kt) {
            __syncthreads();
            #pragma unroll
            for (int it = 0; it < 4; ++it) {
                int c = tid + it * 128;
                int r = c >> 3, d8 = (c & 7) << 3;
                cpa16(Ks + r * 72 + d8, Kg + (size_t)(kt * 64 + r) * 64 + d8);
                cpa16(Vs + r * 72 + d8, Vg + (size_t)(kt * 64 + r) * 64 + d8);
            }
            asm volatile("cp.async.commit_group;\ncp.async.wait_group 0;\n" ::: "memory");
            __syncthreads();

            float S[8][4] = {};
            #pragma unroll
            for (int nf = 0; nf < 8; ++nf) {
                uint32_t kb[2][4];
                #pragma unroll
                for (int p = 0; p < 2; ++p)
                    ldsm4(kb[p][0], kb[p][1], kb[p][2], kb[p][3],
                          sptr(Ks + (nf * 8 + (lane & 7)) * 72 + p * 32 + ((lane >> 3) << 3)));
                #pragma unroll
                for (int kf = 0; kf < 4; ++kf)
                    mmaf16(S[nf][0], S[nf][1], S[nf][2], S[nf][3],
                           qf[kf][0], qf[kf][1], qf[kf][2], qf[kf][3],
                           kb[kf >> 1][(kf & 1) * 2], kb[kf >> 1][(kf & 1) * 2 + 1]);
            }

            uint32_t pf[4][4];
            #pragma unroll
            for (int nf = 0; nf < 8; ++nf) {
                float p0 = ex2f(S[nf][0] * cj2), p1 = ex2f(S[nf][1] * cj2);
                float p2 = ex2f(S[nf][2] * cj2), p3 = ex2f(S[nf][3] * cj2);
                l0 += p0 + p1; l1 += p2 + p3;
                int kf = nf >> 1;
                if ((nf & 1) == 0) { pf[kf][0] = packh2(p0, p1); pf[kf][1] = packh2(p2, p3); }
                else               { pf[kf][2] = packh2(p0, p1); pf[kf][3] = packh2(p2, p3); }
            }

            #pragma unroll
            for (int kf = 0; kf < 4; ++kf) {
                #pragma unroll
                for (int p = 0; p < 4; ++p) {
                    uint32_t vb[4];
                    ldsm4t(vb[0], vb[1], vb[2], vb[3],
                           sptr(Vs + (kf * 16 + lrow) * 72 + p * 16 + lsel));
                    mmaf16(Oj[2 * p][0], Oj[2 * p][1], Oj[2 * p][2], Oj[2 * p][3],
                           pf[kf][0], pf[kf][1], pf[kf][2], pf[kf][3], vb[0], vb[1]);
                    mmaf16(Oj[2 * p + 1][0], Oj[2 * p + 1][1], Oj[2 * p + 1][2], Oj[2 * p + 1][3],
                           pf[kf][0], pf[kf][1], pf[kf][2], pf[kf][3], vb[2], vb[3]);
                }
            }
        }
        l0 += __shfl_xor_sync(0xffffffffu, l0, 1);
        l0 += __shfl_xor_sync(0xffffffffu, l0, 2);
        l1 += __shfl_xor_sync(0xffffffffu, l1, 1);
        l1 += __shfl_xor_sync(0xffffffffu, l1, 2);
        float inv0 = 0.25f / l0, inv1 = 0.25f / l1;
        #pragma unroll
        for (int nf = 0; nf < 8; ++nf) {
            Of[nf][0] += Oj[nf][0] * inv0; Of[nf][1] += Oj[nf][1] * inv0;
            Of[nf][2] += Oj[nf][2] * inv1; Of[nf][3] += Oj[nf][3] * inv1;
        }
    }

    __syncthreads();
    #pragma unroll
    for (int nf = 0; nf < 8; ++nf) {
        int col = nf * 8 + rr * 2;
        int lq = warp * 16 + gg;
        Qs[col * 72 + lq]           = __float2half(Of[nf][0]);
        Qs[(col + 1) * 72 + lq]     = __float2half(Of[nf][1]);
        Qs[col * 72 + lq + 8]       = __float2half(Of[nf][2]);
        Qs[(col + 1) * 72 + lq + 8] = __float2half(Of[nf][3]);
    }
    __syncthreads();
    __half* Og = g_MH + (((size_t)i * 4 + b) * 512 + h * 64) * 512 + qt * 64;
    #pragma unroll
    for (int it = 0; it < 4; ++it) {
        int c = tid + it * 128;
        int d = c >> 3, q8 = (c & 7) << 3;
        *(uint4*)(Og + (size_t)d * 512 + q8) = *(const uint4*)(Qs + d * 72 + q8);
    }
}

// ---------------- row LayerNorm over E=512 -------------------------------------
__global__ __launch_bounds__(128)
void ln_kernel(const float* __restrict__ in, const float* __restrict__ gw,
               const float* __restrict__ bw, float* __restrict__ out,
               __half* __restrict__ outh)
{
    int row = blockIdx.x;
    int s = row >> 11;
    int t = threadIdx.x;

    float4 xv = ((const float4*)(in + (size_t)row * 512))[t];
    float sum = xv.x + xv.y + xv.z + xv.w;
    float sq  = xv.x * xv.x + xv.y * xv.y + xv.z * xv.z + xv.w * xv.w;
    #pragma unroll
    for (int off = 16; off >= 1; off >>= 1) {
        sum += __shfl_xor_sync(0xffffffffu, sum, off);
        sq  += __shfl_xor_sync(0xffffffffu, sq,  off);
    }
    __shared__ float s_sum[4], s_sq[4];
    int w = t >> 5, lane = t & 31;
    if (lane == 0) { s_sum[w] = sum; s_sq[w] = sq; }
    __syncthreads();
    sum = s_sum[0] + s_sum[1] + s_sum[2] + s_sum[3];
    sq  = s_sq[0]  + s_sq[1]  + s_sq[2]  + s_sq[3];

    float mean = sum * (1.0f / 512.0f);
    float var  = sq  * (1.0f / 512.0f) - mean * mean;
    float inv  = rsqrtf(var + 1e-5f);

    float4 g4 = ((const float4*)(gw + s * 512))[t];
    float4 b4 = ((const float4*)(bw + s * 512))[t];
    float4 o;
    o.x = (xv.x - mean) * inv * g4.x + b4.x;
    o.y = (xv.y - mean) * inv * g4.y + b4.y;
    o.z = (xv.z - mean) * inv * g4.z + b4.z;
    o.w = (xv.w - mean) * inv * g4.w + b4.w;
    ((float4*)(out + (size_t)row * 512))[t] = o;
    if (outh) {
        ((__half2*)(outh + (size_t)row * 512))[t * 2]     = __floats2half2_rn(o.x, o.y);
        ((__half2*)(outh + (size_t)row * 512))[t * 2 + 1] = __floats2half2_rn(o.z, o.w);
    }
}

// ---------------- launch --------------------------------------------------------
extern "C" void kernel_launch(void* const* d_in, const int* in_sizes, int n_in,
                              void* d_out, int out_size)
{
    const float* xs0 = (const float*)d_in[0];
    const float* xs1 = (const float*)d_in[1];
    const float* xs2 = (const float*)d_in[2];
    const float* xs3 = (const float*)d_in[3];
    const float* Wq  = (const float*)d_in[4];
    const float* Wk  = (const float*)d_in[5];
    const float* Wv  = (const float*)d_in[6];
    const float* Wo  = (const float*)d_in[7];
    const float* bo  = (const float*)d_in[8];
    const float* ln1g = (const float*)d_in[9];
    const float* ln1b = (const float*)d_in[10];
    const float* ln2g = (const float*)d_in[11];
    const float* ln2b = (const float*)d_in[12];
    const float* W1  = (const float*)d_in[13];
    const float* bf1 = (const float*)d_in[14];
    const float* W2  = (const float*)d_in[15];
    const float* bf2 = (const float*)d_in[16];
    const float* inter = (const float*)d_in[17];

    __half *wqh, *wkh, *wvh, *woh, *w1h, *w2h, *xh, *mh, *hb, *r1h;
    float *t1, *r1, *t2;
    cudaGetSymbolAddress((void**)&wqh, g_Wqh);
    cudaGetSymbolAddress((void**)&wkh, g_Wkh);
    cudaGetSymbolAddress((void**)&wvh, g_Wvh);
    cudaGetSymbolAddress((void**)&woh, g_Woh);
    cudaGetSymbolAddress((void**)&w1h, g_W1h);
    cudaGetSymbolAddress((void**)&w2h, g_W2h);
    cudaGetSymbolAddress((void**)&xh,  g_Xh);
    cudaGetSymbolAddress((void**)&mh,  g_MH);
    cudaGetSymbolAddress((void**)&hb,  g_HB);
    cudaGetSymbolAddress((void**)&r1h, g_R1h);
    cudaGetSymbolAddress((void**)&t1,  g_T1);
    cudaGetSymbolAddress((void**)&r1,  g_R1);
    cudaGetSymbolAddress((void**)&t2,  g_T2);

    // fused conversion: 10 segments, 1024 elems per block
    CvtDesc cd;
    const int SW = 1024;
    const int BW = 4096;
    cd.src[0] = Wq;  cd.dst[0] = wqh;
    cd.src[1] = Wk;  cd.dst[1] = wkh;
    cd.src[2] = Wv;  cd.dst[2] = wvh;
    cd.src[3] = Wo;  cd.dst[3] = woh;
    cd.src[4] = W1;  cd.dst[4] = w1h;
    cd.src[5] = W2;  cd.dst[5] = w2h;
    cd.src[6] = xs0; cd.dst[6] = xh;
    cd.src[7] = xs1; cd.dst[7] = xh + 1 * (size_t)MROWS * EMB;
    cd.src[8] = xs2; cd.dst[8] = xh + 2 * (size_t)MROWS * EMB;
    cd.src[9] = xs3; cd.dst[9] = xh + 3 * (size_t)MROWS * EMB;
    cd.start[0] = 0;
    cd.start[1] = SW;     cd.start[2] = 2 * SW;  cd.start[3] = 3 * SW;
    cd.start[4] = 4 * SW; cd.start[5] = 4 * SW + BW;
    cd.start[6] = 4 * SW + 2 * BW;
    cd.start[7] = cd.start[6] + SW;
    cd.start[8] = cd.start[7] + SW;
    cd.start[9] = cd.start[8] + SW;
    cd.start[10] = cd.start[9] + SW;   // 16384

    cvt_all<<<cd.start[10], 256>>>(cd);

    // QKV projections
    qkv_mma<<<dim3(4, 16, 12), 256>>>();

    // cross-stream attention
    attn_h<<<dim3(8, 8, 16), 128>>>(inter);

    // T1 = MH @ Wo + bo + x   (64-row tiles -> 512 CTAs, 2+ waves)
    R4 rx; rx.p[0] = xs0; rx.p[1] = xs1; rx.p[2] = xs2; rx.p[3] = xs3;
    gemm_bias_resid64<<<dim3(4, 32, 4), 256>>>(mh, woh, bo, rx, t1, MROWS, EMB, EMB);

    // R1 = LN1(T1)  (fp32 + fp16 copies)
    ln_kernel<<<8192, 128>>>(t1, ln1g, ln1b, r1, r1h);

    // HB = gelu(R1h @ W1 + bf1)
    gemm_bias_gelu<<<dim3(16, 16, 4), 256>>>(r1h, w1h, bf1, hb, MROWS, 4 * EMB, EMB);

    // T2 = HB @ W2 + bf2 + R1  (64-row tiles)
    R4 rr; for (int s = 0; s < 4; ++s) rr.p[s] = r1 + (size_t)s * MROWS * EMB;
    gemm_bias_resid64<<<dim3(4, 32, 4), 256>>>(hb, w2h, bf2, rr, t2, MROWS, EMB, 2048);

    // out = LN2(T2)
    ln_kernel<<<8192, 128>>>(t2, ln2g, ln2b, (float*)d_out, nullptr);
}

// round 12
// speedup vs baseline: 1.0281x; 1.0281x over previous
#include <cuda_runtime.h>
#include <cuda_fp16.h>
#include <math.h>
#include <stdint.h>

#define MROWS 2048
#define EMB   512

// ---------------- scratch (device globals) -----------------------------------
__device__ float  g_T1 [4UL*2048*512];
__device__ float  g_R1 [4UL*2048*512];
__device__ float  g_T2 [4UL*2048*512];
__device__ __half g_Xh [4UL*2048*512];
__device__ __half g_Q  [4UL*2048*512];   // [s,b,h,t,d]
__device__ __half g_K  [4UL*2048*512];
__device__ __half g_V  [4UL*2048*512];
__device__ __half g_MH [4UL*2048*512];   // pre-transposed attention out
__device__ __half g_R1h[4UL*2048*512];
__device__ __half g_HB [4UL*2048*2048];
__device__ __half g_Wqh[4UL*512*512];
__device__ __half g_Wkh[4UL*512*512];
__device__ __half g_Wvh[4UL*512*512];
__device__ __half g_Woh[4UL*512*512];
__device__ __half g_W1h[4UL*512*2048];
__device__ __half g_W2h[4UL*2048*512];

struct R4 { const float* p[4]; };
struct CvtDesc {
    const float* src[10];
    __half* dst[10];
    int start[11];
};

__device__ __forceinline__ float gelu_exact(float x) {
    return 0.5f * x * (1.0f + erff(x * 0.70710678118654752440f));
}
__device__ __forceinline__ uint32_t sptr(const void* p) {
    return (uint32_t)__cvta_generic_to_shared(p);
}
__device__ __forceinline__ void cpa16(void* s, const void* g) {
    asm volatile("cp.async.cg.shared.global [%0],[%1],16;\n" :: "r"(sptr(s)), "l"(g));
}
__device__ __forceinline__ void ldsm4(uint32_t& r0, uint32_t& r1, uint32_t& r2,
                                      uint32_t& r3, uint32_t a) {
    asm volatile("ldmatrix.sync.aligned.m8n8.x4.shared.b16 {%0,%1,%2,%3},[%4];\n"
        : "=r"(r0), "=r"(r1), "=r"(r2), "=r"(r3) : "r"(a));
}
__device__ __forceinline__ void ldsm4t(uint32_t& r0, uint32_t& r1, uint32_t& r2,
                                       uint32_t& r3, uint32_t a) {
    asm volatile("ldmatrix.sync.aligned.m8n8.x4.trans.shared.b16 {%0,%1,%2,%3},[%4];\n"
        : "=r"(r0), "=r"(r1), "=r"(r2), "=r"(r3) : "r"(a));
}
__device__ __forceinline__ void mmaf16(float& d0, float& d1, float& d2, float& d3,
    uint32_t a0, uint32_t a1, uint32_t a2, uint32_t a3, uint32_t b0, uint32_t b1) {
    asm volatile("mma.sync.aligned.m16n8k16.row.col.f32.f16.f16.f32 "
        "{%0,%1,%2,%3},{%4,%5,%6,%7},{%8,%9},{%0,%1,%2,%3};\n"
        : "+f"(d0), "+f"(d1), "+f"(d2), "+f"(d3)
        : "r"(a0), "r"(a1), "r"(a2), "r"(a3), "r"(b0), "r"(b1));
}
__device__ __forceinline__ uint32_t packh2(float x, float y) {
    __half2 h = __floats2half2_rn(x, y);
    return *(uint32_t*)&h;
}
__device__ __forceinline__ float ex2f(float x) {
    float y; asm("ex2.approx.f32 %0, %1;" : "=f"(y) : "f"(x)); return y;
}

// ---------------- single fused fp32->fp16 converter ----------------------------
__global__ __launch_bounds__(256)
void cvt_all(CvtDesc d)
{
    int b = blockIdx.x;
    int seg = 0;
    #pragma unroll
    for (int k = 0; k < 9; ++k)
        if (b >= d.start[seg + 1]) ++seg;
    int off = (b - d.start[seg]) * 1024 + threadIdx.x * 4;
    float4 v = *(const float4*)(d.src[seg] + off);
    __half* o = d.dst[seg] + off;
    *(__half2*)(o)     = __floats2half2_rn(v.x, v.y);
    *(__half2*)(o + 2) = __floats2half2_rn(v.z, v.w);
}

// ---------------- fp16 MMA GEMM core: 128x128x32, 256 thr, 2-stage -------------
#define LDA 40
#define LDB 152
#define AS_SZ (128*LDA)
#define BS_SZ (32*LDB)

__device__ __forceinline__ void stage_h(const __half* Ag, const __half* Bg,
    int K, int N, __half* Ad, __half* Bd, int tid)
{
    #pragma unroll
    for (int i = 0; i < 2; ++i) {
        int c = tid + (i << 8);
        int ar = c >> 2, ac = (c & 3) << 3;
        cpa16(Ad + ar * LDA + ac, Ag + (size_t)ar * K + ac);
        int br = c >> 4, bn = (c & 15) << 3;
        cpa16(Bd + br * LDB + bn, Bg + (size_t)br * N + bn);
    }
    asm volatile("cp.async.commit_group;\n" ::: "memory");
}

__device__ __forceinline__ void mainloop_h(
    const __half* __restrict__ A, const __half* __restrict__ B,
    int K, int N, int m0, int n0, float (&acc)[4][4][4],
    __half* As, __half* Bs)
{
    const int tid = threadIdx.x, lane = tid & 31, warp = tid >> 5;
    const int wm = (warp & 1) * 64, wn = (warp >> 1) * 32;
    const int KT = K >> 5;
    const int lrow = lane & 15, lsel = (lane >> 4) << 3;

    stage_h(A + (size_t)m0 * K, B + n0, K, N, As, Bs, tid);

    for (int kt = 0; kt < KT; ++kt) {
        int buf = kt & 1;
        if (kt + 1 < KT) {
            stage_h(A + (size_t)m0 * K + (kt + 1) * 32,
                    B + (size_t)(kt + 1) * 32 * N + n0, K, N,
                    As + (buf ^ 1) * AS_SZ, Bs + (buf ^ 1) * BS_SZ, tid);
            asm volatile("cp.async.wait_group 1;\n" ::: "memory");
        } else {
            asm volatile("cp.async.wait_group 0;\n" ::: "memory");
        }
        __syncthreads();
        const __half* Ad = As + buf * AS_SZ;
        const __half* Bd = Bs + buf * BS_SZ;
        #pragma unroll
        for (int kk = 0; kk < 2; ++kk) {
            int kb = kk * 16;
            uint32_t af[4][4], bf[2][4];
            #pragma unroll
            for (int mi = 0; mi < 4; ++mi)
                ldsm4(af[mi][0], af[mi][1], af[mi][2], af[mi][3],
                      sptr(Ad + (wm + mi * 16 + lrow) * LDA + kb + lsel));
            #pragma unroll
            for (int p = 0; p < 2; ++p)
                ldsm4t(bf[p][0], bf[p][1], bf[p][2], bf[p][3],
                       sptr(Bd + (kb + lrow) * LDB + wn + p * 16 + lsel));
            #pragma unroll
            for (int mi = 0; mi < 4; ++mi)
                #pragma unroll
                for (int ni = 0; ni < 4; ++ni)
                    mmaf16(acc[mi][ni][0], acc[mi][ni][1], acc[mi][ni][2], acc[mi][ni][3],
                           af[mi][0], af[mi][1], af[mi][2], af[mi][3],
                           bf[ni >> 1][(ni & 1) * 2], bf[ni >> 1][(ni & 1) * 2 + 1]);
        }
        __syncthreads();
    }
}

// ---------------- 64x128 variant (short-K single-wave GEMM: Wo only) -----------
#define AS64 (64*LDA)

__device__ __forceinline__ void stage_h64(const __half* Ag, const __half* Bg,
    int K, int N, __half* Ad, __half* Bd, int tid)
{
    {
        int ar = tid >> 2, ac = (tid & 3) << 3;
        cpa16(Ad + ar * LDA + ac, Ag + (size_t)ar * K + ac);
    }
    #pragma unroll
    for (int i = 0; i < 2; ++i) {
        int c = tid + (i << 8);
        int br = c >> 4, bn = (c & 15) << 3;
        cpa16(Bd + br * LDB + bn, Bg + (size_t)br * N + bn);
    }
    asm volatile("cp.async.commit_group;\n" ::: "memory");
}

__device__ __forceinline__ void mainloop_h64(
    const __half* __restrict__ A, const __half* __restrict__ B,
    int K, int N, int m0, int n0, float (&acc)[2][4][4],
    __half* As, __half* Bs)
{
    const int tid = threadIdx.x, lane = tid & 31, warp = tid >> 5;
    const int wm = (warp & 1) * 32, wn = (warp >> 1) * 32;
    const int KT = K >> 5;
    const int lrow = lane & 15, lsel = (lane >> 4) << 3;

    stage_h64(A + (size_t)m0 * K, B + n0, K, N, As, Bs, tid);

    for (int kt = 0; kt < KT; ++kt) {
        int buf = kt & 1;
        if (kt + 1 < KT) {
            stage_h64(A + (size_t)m0 * K + (kt + 1) * 32,
                      B + (size_t)(kt + 1) * 32 * N + n0, K, N,
                      As + (buf ^ 1) * AS64, Bs + (buf ^ 1) * BS_SZ, tid);
            asm volatile("cp.async.wait_group 1;\n" ::: "memory");
        } else {
            asm volatile("cp.async.wait_group 0;\n" ::: "memory");
        }
        __syncthreads();
        const __half* Ad = As + buf * AS64;
        const __half* Bd = Bs + buf * BS_SZ;
        #pragma unroll
        for (int kk = 0; kk < 2; ++kk) {
            int kb = kk * 16;
            uint32_t af[2][4], bf[2][4];
            #pragma unroll
            for (int mi = 0; mi < 2; ++mi)
                ldsm4(af[mi][0], af[mi][1], af[mi][2], af[mi][3],
                      sptr(Ad + (wm + mi * 16 + lrow) * LDA + kb + lsel));
            #pragma unroll
            for (int p = 0; p < 2; ++p)
                ldsm4t(bf[p][0], bf[p][1], bf[p][2], bf[p][3],
                       sptr(Bd + (kb + lrow) * LDB + wn + p * 16 + lsel));
            #pragma unroll
            for (int mi = 0; mi < 2; ++mi)
                #pragma unroll
                for (int ni = 0; ni < 4; ++ni)
                    mmaf16(acc[mi][ni][0], acc[mi][ni][1], acc[mi][ni][2], acc[mi][ni][3],
                           af[mi][0], af[mi][1], af[mi][2], af[mi][3],
                           bf[ni >> 1][(ni & 1) * 2], bf[ni >> 1][(ni & 1) * 2 + 1]);
        }
        __syncthreads();
    }
}

// ---------------- QKV: Xh @ W -> scatter half [s,b,h,t,d] --------------------
__global__ __launch_bounds__(256)
void qkv_mma()
{
    __shared__ __half As[2 * AS_SZ];
    __shared__ __half Bs[2 * BS_SZ];
    int z = blockIdx.z; int s = z / 3, p = z - 3 * s;
    const __half* A = g_Xh + (size_t)s * MROWS * EMB;
    const __half* W = (p == 0 ? g_Wqh : (p == 1 ? g_Wkh : g_Wvh)) + (size_t)s * EMB * EMB;
    __half* O = (p == 0 ? g_Q : (p == 1 ? g_K : g_V));
    int m0 = blockIdx.y * 128, n0 = blockIdx.x * 128;

    float acc[4][4][4] = {};
    mainloop_h(A, W, EMB, EMB, m0, n0, acc, As, Bs);

    const int lane = threadIdx.x & 31, warp = threadIdx.x >> 5;
    const int wm = (warp & 1) * 64, wn = (warp >> 1) * 32;
    const int gg = lane >> 2, rr = lane & 3;
    #pragma unroll
    for (int mi = 0; mi < 4; ++mi) {
        int r0 = m0 + wm + mi * 16 + gg;
        #pragma unroll
        for (int ni = 0; ni < 4; ++ni) {
            int c = n0 + wn + ni * 8 + rr * 2;
            int hh = c >> 6, d = c & 63;
            #pragma unroll
            for (int hr = 0; hr < 2; ++hr) {
                int rw = r0 + hr * 8;
                int b = rw >> 9, t = rw & 511;
                size_t dst = ((((size_t)s * 4 + b) * 8 + hh) * 512 + t) * 64 + d;
                __half2 hv = __floats2half2_rn(acc[mi][ni][hr * 2], acc[mi][ni][hr * 2 + 1]);
                *(__half2*)(O + dst) = hv;
            }
        }
    }
}

// ---------------- 64-tile GEMM + bias + resid -> fp32 (Wo only) ----------------
__global__ __launch_bounds__(256)
void gemm_bias_resid64(const __half* __restrict__ Ab, const __half* __restrict__ Bb,
                       const float* __restrict__ biasb, R4 resid,
                       float* __restrict__ Cb, int M, int N, int K)
{
    __shared__ __half As[2 * AS64];
    __shared__ __half Bs[2 * BS_SZ];
    int s = blockIdx.z;
    const __half* A = Ab + (size_t)s * M * K;
    const __half* B = Bb + (size_t)s * K * N;
    const float* bias = biasb + (size_t)s * N;
    const float* R = resid.p[s];
    float* C = Cb + (size_t)s * M * N;
    int m0 = blockIdx.y * 64, n0 = blockIdx.x * 128;

    float acc[2][4][4] = {};
    mainloop_h64(A, B, K, N, m0, n0, acc, As, Bs);

    const int lane = threadIdx.x & 31, warp = threadIdx.x >> 5;
    const int wm = (warp & 1) * 32, wn = (warp >> 1) * 32;
    const int gg = lane >> 2, rr = lane & 3;
    #pragma unroll
    for (int mi = 0; mi < 2; ++mi) {
        int r0 = m0 + wm + mi * 16 + gg;
        #pragma unroll
        for (int ni = 0; ni < 4; ++ni) {
            int c = n0 + wn + ni * 8 + rr * 2;
            float bx = bias[c], by = bias[c + 1];
            #pragma unroll
            for (int hr = 0; hr < 2; ++hr) {
                int rw = r0 + hr * 8;
                float2 rv = *(const float2*)(R + (size_t)rw * N + c);
                float v0 = acc[mi][ni][hr * 2 + 0] + bx + rv.x;
                float v1 = acc[mi][ni][hr * 2 + 1] + by + rv.y;
                *(float2*)(C + (size_t)rw * N + c) = make_float2(v0, v1);
            }
        }
    }
}

// ---------------- 128-tile GEMM + bias + resid -> fp32 (FFN2) ------------------
__global__ __launch_bounds__(256)
void gemm_bias_resid(const __half* __restrict__ Ab, const __half* __restrict__ Bb,
                     const float* __restrict__ biasb, R4 resid,
                     float* __restrict__ Cb, int M, int N, int K)
{
    __shared__ __half As[2 * AS_SZ];
    __shared__ __half Bs[2 * BS_SZ];
    int s = blockIdx.z;
    const __half* A = Ab + (size_t)s * M * K;
    const __half* B = Bb + (size_t)s * K * N;
    const float* bias = biasb + (size_t)s * N;
    const float* R = resid.p[s];
    float* C = Cb + (size_t)s * M * N;
    int m0 = blockIdx.y * 128, n0 = blockIdx.x * 128;

    float acc[4][4][4] = {};
    mainloop_h(A, B, K, N, m0, n0, acc, As, Bs);

    const int lane = threadIdx.x & 31, warp = threadIdx.x >> 5;
    const int wm = (warp & 1) * 64, wn = (warp >> 1) * 32;
    const int gg = lane >> 2, rr = lane & 3;
    #pragma unroll
    for (int mi = 0; mi < 4; ++mi) {
        int r0 = m0 + wm + mi * 16 + gg;
        #pragma unroll
        for (int ni = 0; ni < 4; ++ni) {
            int c = n0 + wn + ni * 8 + rr * 2;
            float bx = bias[c], by = bias[c + 1];
            #pragma unroll
            for (int hr = 0; hr < 2; ++hr) {
                int rw = r0 + hr * 8;
                float2 rv = *(const float2*)(R + (size_t)rw * N + c);
                float v0 = acc[mi][ni][hr * 2 + 0] + bx + rv.x;
                float v1 = acc[mi][ni][hr * 2 + 1] + by + rv.y;
                *(float2*)(C + (size_t)rw * N + c) = make_float2(v0, v1);
            }
        }
    }
}

// ---------------- GEMM + bias + gelu -> fp16 (FFN1) ----------------------------
__global__ __launch_bounds__(256)
void gemm_bias_gelu(const __half* __restrict__ Ab, const __half* __restrict__ Bb,
                    const float* __restrict__ biasb, __half* __restrict__ Cb,
                    int M, int N, int K)
{
    __shared__ __half As[2 * AS_SZ];
    __shared__ __half Bs[2 * BS_SZ];
    int s = blockIdx.z;
    const __half* A = Ab + (size_t)s * M * K;
    const __half* B = Bb + (size_t)s * K * N;
    const float* bias = biasb + (size_t)s * N;
    __half* C = Cb + (size_t)s * M * N;
    int m0 = blockIdx.y * 128, n0 = blockIdx.x * 128;

    float acc[4][4][4] = {};
    mainloop_h(A, B, K, N, m0, n0, acc, As, Bs);

    const int lane = threadIdx.x & 31, warp = threadIdx.x >> 5;
    const int wm = (warp & 1) * 64, wn = (warp >> 1) * 32;
    const int gg = lane >> 2, rr = lane & 3;
    #pragma unroll
    for (int mi = 0; mi < 4; ++mi) {
        int r0 = m0 + wm + mi * 16 + gg;
        #pragma unroll
        for (int ni = 0; ni < 4; ++ni) {
            int c = n0 + wn + ni * 8 + rr * 2;
            float bx = bias[c], by = bias[c + 1];
            #pragma unroll
            for (int hr = 0; hr < 2; ++hr) {
                int rw = r0 + hr * 8;
                float v0 = gelu_exact(acc[mi][ni][hr * 2 + 0] + bx);
                float v1 = gelu_exact(acc[mi][ni][hr * 2 + 1] + by);
                *(__half2*)(C + (size_t)rw * N + c) = __floats2half2_rn(v0, v1);
            }
        }
    }
}

// ---------------- cross-stream flash attention (serial KV, no-max softmax) -----
__global__ __launch_bounds__(128)
void attn_h(const float* __restrict__ inter)
{
    __shared__ __half Qs[64 * 72];
    __shared__ __half Ks[64 * 72];
    __shared__ __half Vs[64 * 72];

    const int tid = threadIdx.x, lane = tid & 31, warp = tid >> 5;
    const int qt = blockIdx.x, h = blockIdx.y, ib = blockIdx.z;
    const int i = ib >> 2, b = ib & 3;
    const int gg = lane >> 2, rr = lane & 3;
    const int lrow = lane & 15, lsel = (lane >> 4) << 3;

    const __half* Qg = g_Q + ((((size_t)i * 4 + b) * 8 + h) * 512 + qt * 64) * 64;
    #pragma unroll
    for (int it = 0; it < 4; ++it) {
        int c = tid + it * 128;
        int q = c >> 3, d8 = (c & 7) << 3;
        cpa16(Qs + q * 72 + d8, Qg + q * 64 + d8);
    }
    asm volatile("cp.async.commit_group;\ncp.async.wait_group 0;\n" ::: "memory");
    __syncthreads();

    uint32_t qf[4][4];
    #pragma unroll
    for (int kf = 0; kf < 4; ++kf)
        ldsm4(qf[kf][0], qf[kf][1], qf[kf][2], qf[kf][3],
              sptr(Qs + (warp * 16 + lrow) * 72 + kf * 16 + lsel));

    float Of[8][4] = {};
    for (int j = 0; j < 4; ++j) {
        float cj2 = 0.125f * 1.44269504f * __ldg(inter + i * 4 + j);
        const __half* Kg = g_K + (((size_t)j * 4 + b) * 8 + h) * 512 * 64;
        const __half* Vg = g_V + (((size_t)j * 4 + b) * 8 + h) * 512 * 64;
        float l0 = 0.f, l1 = 0.f;
        float Oj[8][4] = {};

        for (int kt = 0; kt < 8; ++kt) {
            __syncthreads();
            #pragma unroll
            for (int it = 0; it < 4; ++it) {
                int c = tid + it * 128;
                int r = c >> 3, d8 = (c & 7) << 3;
                cpa16(Ks + r * 72 + d8, Kg + (size_t)(kt * 64 + r) * 64 + d8);
                cpa16(Vs + r * 72 + d8, Vg + (size_t)(kt * 64 + r) * 64 + d8);
            }
            asm volatile("cp.async.commit_group;\ncp.async.wait_group 0;\n" ::: "memory");
            __syncthreads();

            float S[8][4] = {};
            #pragma unroll
            for (int nf = 0; nf < 8; ++nf) {
                uint32_t kb[2][4];
                #pragma unroll
                for (int p = 0; p < 2; ++p)
                    ldsm4(kb[p][0], kb[p][1], kb[p][2], kb[p][3],
                          sptr(Ks + (nf * 8 + (lane & 7)) * 72 + p * 32 + ((lane >> 3) << 3)));
                #pragma unroll
                for (int kf = 0; kf < 4; ++kf)
                    mmaf16(S[nf][0], S[nf][1], S[nf][2], S[nf][3],
                           qf[kf][0], qf[kf][1], qf[kf][2], qf[kf][3],
                           kb[kf >> 1][(kf & 1) * 2], kb[kf >> 1][(kf & 1) * 2 + 1]);
            }

            uint32_t pf[4][4];
            #pragma unroll
            for (int nf = 0; nf < 8; ++nf) {
                float p0 = ex2f(S[nf][0] * cj2), p1 = ex2f(S[nf][1] * cj2);
                float p2 = ex2f(S[nf][2] * cj2), p3 = ex2f(S[nf][3] * cj2);
                l0 += p0 + p1; l1 += p2 + p3;
                int kf = nf >> 1;
                if ((nf & 1) == 0) { pf[kf][0] = packh2(p0, p1); pf[kf][1] = packh2(p2, p3); }
                else               { pf[kf][2] = packh2(p0, p1); pf[kf][3] = packh2(p2, p3); }
            }

            #pragma unroll
            for (int kf = 0; kf < 4; ++kf) {
                #pragma unroll
                for (int p = 0; p < 4; ++p) {
                    uint32_t vb[4];
                    ldsm4t(vb[0], vb[1], vb[2], vb[3],
                           sptr(Vs + (kf * 16 + lrow) * 72 + p * 16 + lsel));
                    mmaf16(Oj[2 * p][0], Oj[2 * p][1], Oj[2 * p][2], Oj[2 * p][3],
                           pf[kf][0], pf[kf][1], pf[kf][2], pf[kf][3], vb[0], vb[1]);
                    mmaf16(Oj[2 * p + 1][0], Oj[2 * p + 1][1], Oj[2 * p + 1][2], Oj[2 * p + 1][3],
                           pf[kf][0], pf[kf][1], pf[kf][2], pf[kf][3], vb[2], vb[3]);
                }
            }
        }
        l0 += __shfl_xor_sync(0xffffffffu, l0, 1);
        l0 += __shfl_xor_sync(0xffffffffu, l0, 2);
        l1 += __shfl_xor_sync(0xffffffffu, l1, 1);
        l1 += __shfl_xor_sync(0xffffffffu, l1, 2);
        float inv0 = 0.25f / l0, inv1 = 0.25f / l1;
        #pragma unroll
        for (int nf = 0; nf < 8; ++nf) {
            Of[nf][0] += Oj[nf][0] * inv0; Of[nf][1] += Oj[nf][1] * inv0;
            Of[nf][2] += Oj[nf][2] * inv1; Of[nf][3] += Oj[nf][3] * inv1;
        }
    }

    __syncthreads();
    #pragma unroll
    for (int nf = 0; nf < 8; ++nf) {
        int col = nf * 8 + rr * 2;
        int lq = warp * 16 + gg;
        Qs[col * 72 + lq]           = __float2half(Of[nf][0]);
        Qs[(col + 1) * 72 + lq]     = __float2half(Of[nf][1]);
        Qs[col * 72 + lq + 8]       = __float2half(Of[nf][2]);
        Qs[(col + 1) * 72 + lq + 8] = __float2half(Of[nf][3]);
    }
    __syncthreads();
    __half* Og = g_MH + (((size_t)i * 4 + b) * 512 + h * 64) * 512 + qt * 64;
    #pragma unroll
    for (int it = 0; it < 4; ++it) {
        int c = tid + it * 128;
        int d = c >> 3, q8 = (c & 7) << 3;
        *(uint4*)(Og + (size_t)d * 512 + q8) = *(const uint4*)(Qs + d * 72 + q8);
    }
}

// ---------------- row LayerNorm over E=512 -------------------------------------
__global__ __launch_bounds__(128)
void ln_kernel(const float* __restrict__ in, const float* __restrict__ gw,
               const float* __restrict__ bw, float* __restrict__ out,
               __half* __restrict__ outh)
{
    int row = blockIdx.x;
    int s = row >> 11;
    int t = threadIdx.x;

    float4 xv = ((const float4*)(in + (size_t)row * 512))[t];
    float sum = xv.x + xv.y + xv.z + xv.w;
    float sq  = xv.x * xv.x + xv.y * xv.y + xv.z * xv.z + xv.w * xv.w;
    #pragma unroll
    for (int off = 16; off >= 1; off >>= 1) {
        sum += __shfl_xor_sync(0xffffffffu, sum, off);
        sq  += __shfl_xor_sync(0xffffffffu, sq,  off);
    }
    __shared__ float s_sum[4], s_sq[4];
    int w = t >> 5, lane = t & 31;
    if (lane == 0) { s_sum[w] = sum; s_sq[w] = sq; }
    __syncthreads();
    sum = s_sum[0] + s_sum[1] + s_sum[2] + s_sum[3];
    sq  = s_sq[0]  + s_sq[1]  + s_sq[2]  + s_sq[3];

    float mean = sum * (1.0f / 512.0f);
    float var  = sq  * (1.0f / 512.0f) - mean * mean;
    float inv  = rsqrtf(var + 1e-5f);

    float4 g4 = ((const float4*)(gw + s * 512))[t];
    float4 b4 = ((const float4*)(bw + s * 512))[t];
    float4 o;
    o.x = (xv.x - mean) * inv * g4.x + b4.x;
    o.y = (xv.y - mean) * inv * g4.y + b4.y;
    o.z = (xv.z - mean) * inv * g4.z + b4.z;
    o.w = (xv.w - mean) * inv * g4.w + b4.w;
    ((float4*)(out + (size_t)row * 512))[t] = o;
    if (outh) {
        ((__half2*)(outh + (size_t)row * 512))[t * 2]     = __floats2half2_rn(o.x, o.y);
        ((__half2*)(outh + (size_t)row * 512))[t * 2 + 1] = __floats2half2_rn(o.z, o.w);
    }
}

// ---------------- launch --------------------------------------------------------
extern "C" void kernel_launch(void* const* d_in, const int* in_sizes, int n_in,
                              void* d_out, int out_size)
{
    const float* xs0 = (const float*)d_in[0];
    const float* xs1 = (const float*)d_in[1];
    const float* xs2 = (const float*)d_in[2];
    const float* xs3 = (const float*)d_in[3];
    const float* Wq  = (const float*)d_in[4];
    const float* Wk  = (const float*)d_in[5];
    const float* Wv  = (const float*)d_in[6];
    const float* Wo  = (const float*)d_in[7];
    const float* bo  = (const float*)d_in[8];
    const float* ln1g = (const float*)d_in[9];
    const float* ln1b = (const float*)d_in[10];
    const float* ln2g = (const float*)d_in[11];
    const float* ln2b = (const float*)d_in[12];
    const float* W1  = (const float*)d_in[13];
    const float* bf1 = (const float*)d_in[14];
    const float* W2  = (const float*)d_in[15];
    const float* bf2 = (const float*)d_in[16];
    const float* inter = (const float*)d_in[17];

    __half *wqh, *wkh, *wvh, *woh, *w1h, *w2h, *xh, *mh, *hb, *r1h;
    float *t1, *r1, *t2;
    cudaGetSymbolAddress((void**)&wqh, g_Wqh);
    cudaGetSymbolAddress((void**)&wkh, g_Wkh);
    cudaGetSymbolAddress((void**)&wvh, g_Wvh);
    cudaGetSymbolAddress((void**)&woh, g_Woh);
    cudaGetSymbolAddress((void**)&w1h, g_W1h);
    cudaGetSymbolAddress((void**)&w2h, g_W2h);
    cudaGetSymbolAddress((void**)&xh,  g_Xh);
    cudaGetSymbolAddress((void**)&mh,  g_MH);
    cudaGetSymbolAddress((void**)&hb,  g_HB);
    cudaGetSymbolAddress((void**)&r1h, g_R1h);
    cudaGetSymbolAddress((void**)&t1,  g_T1);
    cudaGetSymbolAddress((void**)&r1,  g_R1);
    cudaGetSymbolAddress((void**)&t2,  g_T2);

    // fused conversion: 10 segments, 1024 elems per block
    CvtDesc cd;
    const int SW = 1024;
    const int BW = 4096;
    cd.src[0] = Wq;  cd.dst[0] = wqh;
    cd.src[1] = Wk;  cd.dst[1] = wkh;
    cd.src[2] = Wv;  cd.dst[2] = wvh;
    cd.src[3] = Wo;  cd.dst[3] = woh;
    cd.src[4] = W1;  cd.dst[4] = w1h;
    cd.src[5] = W2;  cd.dst[5] = w2h;
    cd.src[6] = xs0; cd.dst[6] = xh;
    cd.src[7] = xs1; cd.dst[7] = xh + 1 * (size_t)MROWS * EMB;
    cd.src[8] = xs2; cd.dst[8] = xh + 2 * (size_t)MROWS * EMB;
    cd.src[9] = xs3; cd.dst[9] = xh + 3 * (size_t)MROWS * EMB;
    cd.start[0] = 0;
    cd.start[1] = SW;     cd.start[2] = 2 * SW;  cd.start[3] = 3 * SW;
    cd.start[4] = 4 * SW; cd.start[5] = 4 * SW + BW;
    cd.start[6] = 4 * SW + 2 * BW;
    cd.start[7] = cd.start[6] + SW;
    cd.start[8] = cd.start[7] + SW;
    cd.start[9] = cd.start[8] + SW;
    cd.start[10] = cd.start[9] + SW;   // 16384

    cvt_all<<<cd.start[10], 256>>>(cd);

    // QKV projections
    qkv_mma<<<dim3(4, 16, 12), 256>>>();

    // cross-stream attention
    attn_h<<<dim3(8, 8, 16), 128>>>(inter);

    // T1 = MH @ Wo + bo + x   (64-row tiles: short-K single-wave case)
    R4 rx; rx.p[0] = xs0; rx.p[1] = xs1; rx.p[2] = xs2; rx.p[3] = xs3;
    gemm_bias_resid64<<<dim3(4, 32, 4), 256>>>(mh, woh, bo, rx, t1, MROWS, EMB, EMB);

    // R1 = LN1(T1)  (fp32 + fp16 copies)
    ln_kernel<<<8192, 128>>>(t1, ln1g, ln1b, r1, r1h);

    // HB = gelu(R1h @ W1 + bf1)
    gemm_bias_gelu<<<dim3(16, 16, 4), 256>>>(r1h, w1h, bf1, hb, MROWS, 4 * EMB, EMB);

    // T2 = HB @ W2 + bf2 + R1  (128-row tiles: long-K case)
    R4 rr; for (int s = 0; s < 4; ++s) rr.p[s] = r1 + (size_t)s * MROWS * EMB;
    gemm_bias_resid<<<dim3(4, 16, 4), 256>>>(hb, w2h, bf2, rr, t2, MROWS, EMB, 2048);

    // out = LN2(T2)
    ln_kernel<<<8192, 128>>>(t2, ln2g, ln2b, (float*)d_out, nullptr);
}

// round 13
// speedup vs baseline: 1.0429x; 1.0144x over previous
#include <cuda_runtime.h>
#include <cuda_fp16.h>
#include <math.h>
#include <stdint.h>

#define MROWS 2048
#define EMB   512

// ---------------- scratch (device globals) -----------------------------------
__device__ float  g_T1 [4UL*2048*512];
__device__ float  g_R1 [4UL*2048*512];
__device__ float  g_T2 [4UL*2048*512];
__device__ __half g_Xh [4UL*2048*512];
__device__ __half g_Q  [4UL*2048*512];   // [s,b,h,t,d]
__device__ __half g_K  [4UL*2048*512];
__device__ __half g_V  [4UL*2048*512];
__device__ __half g_MH [4UL*2048*512];   // pre-transposed attention out
__device__ __half g_R1h[4UL*2048*512];
__device__ __half g_HB [4UL*2048*2048];
__device__ __half g_Wqh[4UL*512*512];
__device__ __half g_Wkh[4UL*512*512];
__device__ __half g_Wvh[4UL*512*512];
__device__ __half g_Woh[4UL*512*512];
__device__ __half g_W1h[4UL*512*2048];
__device__ __half g_W2h[4UL*2048*512];

struct R4 { const float* p[4]; };
struct CvtDesc {
    const float* src[10];
    __half* dst[10];
    int start[11];
};

__device__ __forceinline__ float gelu_exact(float x) {
    return 0.5f * x * (1.0f + erff(x * 0.70710678118654752440f));
}
__device__ __forceinline__ uint32_t sptr(const void* p) {
    return (uint32_t)__cvta_generic_to_shared(p);
}
__device__ __forceinline__ void cpa16(void* s, const void* g) {
    asm volatile("cp.async.cg.shared.global [%0],[%1],16;\n" :: "r"(sptr(s)), "l"(g));
}
__device__ __forceinline__ void ldsm4(uint32_t& r0, uint32_t& r1, uint32_t& r2,
                                      uint32_t& r3, uint32_t a) {
    asm volatile("ldmatrix.sync.aligned.m8n8.x4.shared.b16 {%0,%1,%2,%3},[%4];\n"
        : "=r"(r0), "=r"(r1), "=r"(r2), "=r"(r3) : "r"(a));
}
__device__ __forceinline__ void ldsm4t(uint32_t& r0, uint32_t& r1, uint32_t& r2,
                                       uint32_t& r3, uint32_t a) {
    asm volatile("ldmatrix.sync.aligned.m8n8.x4.trans.shared.b16 {%0,%1,%2,%3},[%4];\n"
        : "=r"(r0), "=r"(r1), "=r"(r2), "=r"(r3) : "r"(a));
}
__device__ __forceinline__ void mmaf16(float& d0, float& d1, float& d2, float& d3,
    uint32_t a0, uint32_t a1, uint32_t a2, uint32_t a3, uint32_t b0, uint32_t b1) {
    asm volatile("mma.sync.aligned.m16n8k16.row.col.f32.f16.f16.f32 "
        "{%0,%1,%2,%3},{%4,%5,%6,%7},{%8,%9},{%0,%1,%2,%3};\n"
        : "+f"(d0), "+f"(d1), "+f"(d2), "+f"(d3)
        : "r"(a0), "r"(a1), "r"(a2), "r"(a3), "r"(b0), "r"(b1));
}
__device__ __forceinline__ uint32_t packh2(float x, float y) {
    __half2 h = __floats2half2_rn(x, y);
    return *(uint32_t*)&h;
}
__device__ __forceinline__ float ex2f(float x) {
    float y; asm("ex2.approx.f32 %0, %1;" : "=f"(y) : "f"(x)); return y;
}

// ---------------- fused fp32->fp16 converter (4 float4 per thread) -------------
__global__ __launch_bounds__(256)
void cvt_all(CvtDesc d)
{
    int b = blockIdx.x;
    int seg = 0;
    #pragma unroll
    for (int k = 0; k < 9; ++k)
        if (b >= d.start[seg + 1]) ++seg;
    int base = (b - d.start[seg]) * 4096 + threadIdx.x * 4;
    const float* s = d.src[seg];
    __half* o = d.dst[seg];
    float4 v[4];
    #pragma unroll
    for (int i = 0; i < 4; ++i)
        v[i] = *(const float4*)(s + base + i * 1024);
    #pragma unroll
    for (int i = 0; i < 4; ++i) {
        int off = base + i * 1024;
        *(__half2*)(o + off)     = __floats2half2_rn(v[i].x, v[i].y);
        *(__half2*)(o + off + 2) = __floats2half2_rn(v[i].z, v[i].w);
    }
}

// ---------------- fp16 MMA GEMM core: 128x128x32, 256 thr, 2-stage -------------
#define LDA 40
#define LDB 152
#define AS_SZ (128*LDA)
#define BS_SZ (32*LDB)

__device__ __forceinline__ void stage_h(const __half* Ag, const __half* Bg,
    int K, int N, __half* Ad, __half* Bd, int tid)
{
    #pragma unroll
    for (int i = 0; i < 2; ++i) {
        int c = tid + (i << 8);
        int ar = c >> 2, ac = (c & 3) << 3;
        cpa16(Ad + ar * LDA + ac, Ag + (size_t)ar * K + ac);
        int br = c >> 4, bn = (c & 15) << 3;
        cpa16(Bd + br * LDB + bn, Bg + (size_t)br * N + bn);
    }
    asm volatile("cp.async.commit_group;\n" ::: "memory");
}

__device__ __forceinline__ void mainloop_h(
    const __half* __restrict__ A, const __half* __restrict__ B,
    int K, int N, int m0, int n0, float (&acc)[4][4][4],
    __half* As, __half* Bs)
{
    const int tid = threadIdx.x, lane = tid & 31, warp = tid >> 5;
    const int wm = (warp & 1) * 64, wn = (warp >> 1) * 32;
    const int KT = K >> 5;
    const int lrow = lane & 15, lsel = (lane >> 4) << 3;

    stage_h(A + (size_t)m0 * K, B + n0, K, N, As, Bs, tid);

    for (int kt = 0; kt < KT; ++kt) {
        int buf = kt & 1;
        if (kt + 1 < KT) {
            stage_h(A + (size_t)m0 * K + (kt + 1) * 32,
                    B + (size_t)(kt + 1) * 32 * N + n0, K, N,
                    As + (buf ^ 1) * AS_SZ, Bs + (buf ^ 1) * BS_SZ, tid);
            asm volatile("cp.async.wait_group 1;\n" ::: "memory");
        } else {
            asm volatile("cp.async.wait_group 0;\n" ::: "memory");
        }
        __syncthreads();
        const __half* Ad = As + buf * AS_SZ;
        const __half* Bd = Bs + buf * BS_SZ;
        #pragma unroll
        for (int kk = 0; kk < 2; ++kk) {
            int kb = kk * 16;
            uint32_t af[4][4], bf[2][4];
            #pragma unroll
            for (int mi = 0; mi < 4; ++mi)
                ldsm4(af[mi][0], af[mi][1], af[mi][2], af[mi][3],
                      sptr(Ad + (wm + mi * 16 + lrow) * LDA + kb + lsel));
            #pragma unroll
            for (int p = 0; p < 2; ++p)
                ldsm4t(bf[p][0], bf[p][1], bf[p][2], bf[p][3],
                       sptr(Bd + (kb + lrow) * LDB + wn + p * 16 + lsel));
            #pragma unroll
            for (int mi = 0; mi < 4; ++mi)
                #pragma unroll
                for (int ni = 0; ni < 4; ++ni)
                    mmaf16(acc[mi][ni][0], acc[mi][ni][1], acc[mi][ni][2], acc[mi][ni][3],
                           af[mi][0], af[mi][1], af[mi][2], af[mi][3],
                           bf[ni >> 1][(ni & 1) * 2], bf[ni >> 1][(ni & 1) * 2 + 1]);
        }
        __syncthreads();
    }
}

// ---------------- 64x128 variant (short-K single-wave GEMM: Wo only) -----------
#define AS64 (64*LDA)

__device__ __forceinline__ void stage_h64(const __half* Ag, const __half* Bg,
    int K, int N, __half* Ad, __half* Bd, int tid)
{
    {
        int ar = tid >> 2, ac = (tid & 3) << 3;
        cpa16(Ad + ar * LDA + ac, Ag + (size_t)ar * K + ac);
    }
    #pragma unroll
    for (int i = 0; i < 2; ++i) {
        int c = tid + (i << 8);
        int br = c >> 4, bn = (c & 15) << 3;
        cpa16(Bd + br * LDB + bn, Bg + (size_t)br * N + bn);
    }
    asm volatile("cp.async.commit_group;\n" ::: "memory");
}

__device__ __forceinline__ void mainloop_h64(
    const __half* __restrict__ A, const __half* __restrict__ B,
    int K, int N, int m0, int n0, float (&acc)[2][4][4],
    __half* As, __half* Bs)
{
    const int tid = threadIdx.x, lane = tid & 31, warp = tid >> 5;
    const int wm = (warp & 1) * 32, wn = (warp >> 1) * 32;
    const int KT = K >> 5;
    const int lrow = lane & 15, lsel = (lane >> 4) << 3;

    stage_h64(A + (size_t)m0 * K, B + n0, K, N, As, Bs, tid);

    for (int kt = 0; kt < KT; ++kt) {
        int buf = kt & 1;
        if (kt + 1 < KT) {
            stage_h64(A + (size_t)m0 * K + (kt + 1) * 32,
                      B + (size_t)(kt + 1) * 32 * N + n0, K, N,
                      As + (buf ^ 1) * AS64, Bs + (buf ^ 1) * BS_SZ, tid);
            asm volatile("cp.async.wait_group 1;\n" ::: "memory");
        } else {
            asm volatile("cp.async.wait_group 0;\n" ::: "memory");
        }
        __syncthreads();
        const __half* Ad = As + buf * AS64;
        const __half* Bd = Bs + buf * BS_SZ;
        #pragma unroll
        for (int kk = 0; kk < 2; ++kk) {
            int kb = kk * 16;
            uint32_t af[2][4], bf[2][4];
            #pragma unroll
            for (int mi = 0; mi < 2; ++mi)
                ldsm4(af[mi][0], af[mi][1], af[mi][2], af[mi][3],
                      sptr(Ad + (wm + mi * 16 + lrow) * LDA + kb + lsel));
            #pragma unroll
            for (int p = 0; p < 2; ++p)
                ldsm4t(bf[p][0], bf[p][1], bf[p][2], bf[p][3],
                       sptr(Bd + (kb + lrow) * LDB + wn + p * 16 + lsel));
            #pragma unroll
            for (int mi = 0; mi < 2; ++mi)
                #pragma unroll
                for (int ni = 0; ni < 4; ++ni)
                    mmaf16(acc[mi][ni][0], acc[mi][ni][1], acc[mi][ni][2], acc[mi][ni][3],
                           af[mi][0], af[mi][1], af[mi][2], af[mi][3],
                           bf[ni >> 1][(ni & 1) * 2], bf[ni >> 1][(ni & 1) * 2 + 1]);
        }
        __syncthreads();
    }
}

// ---------------- QKV: Xh @ W -> scatter half [s,b,h,t,d] --------------------
__global__ __launch_bounds__(256)
void qkv_mma()
{
    __shared__ __half As[2 * AS_SZ];
    __shared__ __half Bs[2 * BS_SZ];
    int z = blockIdx.z; int s = z / 3, p = z - 3 * s;
    const __half* A = g_Xh + (size_t)s * MROWS * EMB;
    const __half* W = (p == 0 ? g_Wqh : (p == 1 ? g_Wkh : g_Wvh)) + (size_t)s * EMB * EMB;
    __half* O = (p == 0 ? g_Q : (p == 1 ? g_K : g_V));
    int m0 = blockIdx.y * 128, n0 = blockIdx.x * 128;

    float acc[4][4][4] = {};
    mainloop_h(A, W, EMB, EMB, m0, n0, acc, As, Bs);

    const int lane = threadIdx.x & 31, warp = threadIdx.x >> 5;
    const int wm = (warp & 1) * 64, wn = (warp >> 1) * 32;
    const int gg = lane >> 2, rr = lane & 3;
    #pragma unroll
    for (int mi = 0; mi < 4; ++mi) {
        int r0 = m0 + wm + mi * 16 + gg;
        #pragma unroll
        for (int ni = 0; ni < 4; ++ni) {
            int c = n0 + wn + ni * 8 + rr * 2;
            int hh = c >> 6, d = c & 63;
            #pragma unroll
            for (int hr = 0; hr < 2; ++hr) {
                int rw = r0 + hr * 8;
                int b = rw >> 9, t = rw & 511;
                size_t dst = ((((size_t)s * 4 + b) * 8 + hh) * 512 + t) * 64 + d;
                __half2 hv = __floats2half2_rn(acc[mi][ni][hr * 2], acc[mi][ni][hr * 2 + 1]);
                *(__half2*)(O + dst) = hv;
            }
        }
    }
}

// ---------------- 64-tile GEMM + bias + resid -> fp32 (Wo only) ----------------
__global__ __launch_bounds__(256)
void gemm_bias_resid64(const __half* __restrict__ Ab, const __half* __restrict__ Bb,
                       const float* __restrict__ biasb, R4 resid,
                       float* __restrict__ Cb, int M, int N, int K)
{
    __shared__ __half As[2 * AS64];
    __shared__ __half Bs[2 * BS_SZ];
    int s = blockIdx.z;
    const __half* A = Ab + (size_t)s * M * K;
    const __half* B = Bb + (size_t)s * K * N;
    const float* bias = biasb + (size_t)s * N;
    const float* R = resid.p[s];
    float* C = Cb + (size_t)s * M * N;
    int m0 = blockIdx.y * 64, n0 = blockIdx.x * 128;

    float acc[2][4][4] = {};
    mainloop_h64(A, B, K, N, m0, n0, acc, As, Bs);

    const int lane = threadIdx.x & 31, warp = threadIdx.x >> 5;
    const int wm = (warp & 1) * 32, wn = (warp >> 1) * 32;
    const int gg = lane >> 2, rr = lane & 3;
    #pragma unroll
    for (int mi = 0; mi < 2; ++mi) {
        int r0 = m0 + wm + mi * 16 + gg;
        #pragma unroll
        for (int ni = 0; ni < 4; ++ni) {
            int c = n0 + wn + ni * 8 + rr * 2;
            float bx = bias[c], by = bias[c + 1];
            #pragma unroll
            for (int hr = 0; hr < 2; ++hr) {
                int rw = r0 + hr * 8;
                float2 rv = *(const float2*)(R + (size_t)rw * N + c);
                float v0 = acc[mi][ni][hr * 2 + 0] + bx + rv.x;
                float v1 = acc[mi][ni][hr * 2 + 1] + by + rv.y;
                *(float2*)(C + (size_t)rw * N + c) = make_float2(v0, v1);
            }
        }
    }
}

// ---------------- 128-tile GEMM + bias + resid -> fp32 (FFN2) ------------------
__global__ __launch_bounds__(256)
void gemm_bias_resid(const __half* __restrict__ Ab, const __half* __restrict__ Bb,
                     const float* __restrict__ biasb, R4 resid,
                     float* __restrict__ Cb, int M, int N, int K)
{
    __shared__ __half As[2 * AS_SZ];
    __shared__ __half Bs[2 * BS_SZ];
    int s = blockIdx.z;
    const __half* A = Ab + (size_t)s * M * K;
    const __half* B = Bb + (size_t)s * K * N;
    const float* bias = biasb + (size_t)s * N;
    const float* R = resid.p[s];
    float* C = Cb + (size_t)s * M * N;
    int m0 = blockIdx.y * 128, n0 = blockIdx.x * 128;

    float acc[4][4][4] = {};
    mainloop_h(A, B, K, N, m0, n0, acc, As, Bs);

    const int lane = threadIdx.x & 31, warp = threadIdx.x >> 5;
    const int wm = (warp & 1) * 64, wn = (warp >> 1) * 32;
    const int gg = lane >> 2, rr = lane & 3;
    #pragma unroll
    for (int mi = 0; mi < 4; ++mi) {
        int r0 = m0 + wm + mi * 16 + gg;
        #pragma unroll
        for (int ni = 0; ni < 4; ++ni) {
            int c = n0 + wn + ni * 8 + rr * 2;
            float bx = bias[c], by = bias[c + 1];
            #pragma unroll
            for (int hr = 0; hr < 2; ++hr) {
                int rw = r0 + hr * 8;
                float2 rv = *(const float2*)(R + (size_t)rw * N + c);
                float v0 = acc[mi][ni][hr * 2 + 0] + bx + rv.x;
                float v1 = acc[mi][ni][hr * 2 + 1] + by + rv.y;
                *(float2*)(C + (size_t)rw * N + c) = make_float2(v0, v1);
            }
        }
    }
}

// ---------------- GEMM + bias + gelu -> fp16 (FFN1) ----------------------------
__global__ __launch_bounds__(256)
void gemm_bias_gelu(const __half* __restrict__ Ab, const __half* __restrict__ Bb,
                    const float* __restrict__ biasb, __half* __restrict__ Cb,
                    int M, int N, int K)
{
    __shared__ __half As[2 * AS_SZ];
    __shared__ __half Bs[2 * BS_SZ];
    int s = blockIdx.z;
    const __half* A = Ab + (size_t)s * M * K;
    const __half* B = Bb + (size_t)s * K * N;
    const float* bias = biasb + (size_t)s * N;
    __half* C = Cb + (size_t)s * M * N;
    int m0 = blockIdx.y * 128, n0 = blockIdx.x * 128;

    float acc[4][4][4] = {};
    mainloop_h(A, B, K, N, m0, n0, acc, As, Bs);

    const int lane = threadIdx.x & 31, warp = threadIdx.x >> 5;
    const int wm = (warp & 1) * 64, wn = (warp >> 1) * 32;
    const int gg = lane >> 2, rr = lane & 3;
    #pragma unroll
    for (int mi = 0; mi < 4; ++mi) {
        int r0 = m0 + wm + mi * 16 + gg;
        #pragma unroll
        for (int ni = 0; ni < 4; ++ni) {
            int c = n0 + wn + ni * 8 + rr * 2;
            float bx = bias[c], by = bias[c + 1];
            #pragma unroll
            for (int hr = 0; hr < 2; ++hr) {
                int rw = r0 + hr * 8;
                float v0 = gelu_exact(acc[mi][ni][hr * 2 + 0] + bx);
                float v1 = gelu_exact(acc[mi][ni][hr * 2 + 1] + by);
                *(__half2*)(C + (size_t)rw * N + c) = __floats2half2_rn(v0, v1);
            }
        }
    }
}

// ---------------- cross-stream flash attention (serial KV, no-max softmax) -----
__global__ __launch_bounds__(128)
void attn_h(const float* __restrict__ inter)
{
    __shared__ __half Qs[64 * 72];
    __shared__ __half Ks[64 * 72];
    __shared__ __half Vs[64 * 72];

    const int tid = threadIdx.x, lane = tid & 31, warp = tid >> 5;
    const int qt = blockIdx.x, h = blockIdx.y, ib = blockIdx.z;
    const int i = ib >> 2, b = ib & 3;
    const int gg = lane >> 2, rr = lane & 3;
    const int lrow = lane & 15, lsel = (lane >> 4) << 3;

    const __half* Qg = g_Q + ((((size_t)i * 4 + b) * 8 + h) * 512 + qt * 64) * 64;
    #pragma unroll
    for (int it = 0; it < 4; ++it) {
        int c = tid + it * 128;
        int q = c >> 3, d8 = (c & 7) << 3;
        cpa16(Qs + q * 72 + d8, Qg + q * 64 + d8);
    }
    asm volatile("cp.async.commit_group;\ncp.async.wait_group 0;\n" ::: "memory");
    __syncthreads();

    uint32_t qf[4][4];
    #pragma unroll
    for (int kf = 0; kf < 4; ++kf)
        ldsm4(qf[kf][0], qf[kf][1], qf[kf][2], qf[kf][3],
              sptr(Qs + (warp * 16 + lrow) * 72 + kf * 16 + lsel));

    float Of[8][4] = {};
    for (int j = 0; j < 4; ++j) {
        float cj2 = 0.125f * 1.44269504f * __ldg(inter + i * 4 + j);
        const __half* Kg = g_K + (((size_t)j * 4 + b) * 8 + h) * 512 * 64;
        const __half* Vg = g_V + (((size_t)j * 4 + b) * 8 + h) * 512 * 64;
        float l0 = 0.f, l1 = 0.f;
        float Oj[8][4] = {};

        for (int kt = 0; kt < 8; ++kt) {
            __syncthreads();
            #pragma unroll
            for (int it = 0; it < 4; ++it) {
                int c = tid + it * 128;
                int r = c >> 3, d8 = (c & 7) << 3;
                cpa16(Ks + r * 72 + d8, Kg + (size_t)(kt * 64 + r) * 64 + d8);
                cpa16(Vs + r * 72 + d8, Vg + (size_t)(kt * 64 + r) * 64 + d8);
            }
            asm volatile("cp.async.commit_group;\ncp.async.wait_group 0;\n" ::: "memory");
            __syncthreads();

            float S[8][4] = {};
            #pragma unroll
            for (int nf = 0; nf < 8; ++nf) {
                uint32_t kb[2][4];
                #pragma unroll
                for (int p = 0; p < 2; ++p)
                    ldsm4(kb[p][0], kb[p][1], kb[p][2], kb[p][3],
                          sptr(Ks + (nf * 8 + (lane & 7)) * 72 + p * 32 + ((lane >> 3) << 3)));
                #pragma unroll
                for (int kf = 0; kf < 4; ++kf)
                    mmaf16(S[nf][0], S[nf][1], S[nf][2], S[nf][3],
                           qf[kf][0], qf[kf][1], qf[kf][2], qf[kf][3],
                           kb[kf >> 1][(kf & 1) * 2], kb[kf >> 1][(kf & 1) * 2 + 1]);
            }

            uint32_t pf[4][4];
            #pragma unroll
            for (int nf = 0; nf < 8; ++nf) {
                float p0 = ex2f(S[nf][0] * cj2), p1 = ex2f(S[nf][1] * cj2);
                float p2 = ex2f(S[nf][2] * cj2), p3 = ex2f(S[nf][3] * cj2);
                l0 += p0 + p1; l1 += p2 + p3;
                int kf = nf >> 1;
                if ((nf & 1) == 0) { pf[kf][0] = packh2(p0, p1); pf[kf][1] = packh2(p2, p3); }
                else               { pf[kf][2] = packh2(p0, p1); pf[kf][3] = packh2(p2, p3); }
            }

            #pragma unroll
            for (int kf = 0; kf < 4; ++kf) {
                #pragma unroll
                for (int p = 0; p < 4; ++p) {
                    uint32_t vb[4];
                    ldsm4t(vb[0], vb[1], vb[2], vb[3],
                           sptr(Vs + (kf * 16 + lrow) * 72 + p * 16 + lsel));
                    mmaf16(Oj[2 * p][0], Oj[2 * p][1], Oj[2 * p][2], Oj[2 * p][3],
                           pf[kf][0], pf[kf][1], pf[kf][2], pf[kf][3], vb[0], vb[1]);
                    mmaf16(Oj[2 * p + 1][0], Oj[2 * p + 1][1], Oj[2 * p + 1][2], Oj[2 * p + 1][3],
                           pf[kf][0], pf[kf][1], pf[kf][2], pf[kf][3], vb[2], vb[3]);
                }
            }
        }
        l0 += __shfl_xor_sync(0xffffffffu, l0, 1);
        l0 += __shfl_xor_sync(0xffffffffu, l0, 2);
        l1 += __shfl_xor_sync(0xffffffffu, l1, 1);
        l1 += __shfl_xor_sync(0xffffffffu, l1, 2);
        float inv0 = 0.25f / l0, inv1 = 0.25f / l1;
        #pragma unroll
        for (int nf = 0; nf < 8; ++nf) {
            Of[nf][0] += Oj[nf][0] * inv0; Of[nf][1] += Oj[nf][1] * inv0;
            Of[nf][2] += Oj[nf][2] * inv1; Of[nf][3] += Oj[nf][3] * inv1;
        }
    }

    __syncthreads();
    #pragma unroll
    for (int nf = 0; nf < 8; ++nf) {
        int col = nf * 8 + rr * 2;
        int lq = warp * 16 + gg;
        Qs[col * 72 + lq]           = __float2half(Of[nf][0]);
        Qs[(col + 1) * 72 + lq]     = __float2half(Of[nf][1]);
        Qs[col * 72 + lq + 8]       = __float2half(Of[nf][2]);
        Qs[(col + 1) * 72 + lq + 8] = __float2half(Of[nf][3]);
    }
    __syncthreads();
    __half* Og = g_MH + (((size_t)i * 4 + b) * 512 + h * 64) * 512 + qt * 64;
    #pragma unroll
    for (int it = 0; it < 4; ++it) {
        int c = tid + it * 128;
        int d = c >> 3, q8 = (c & 7) << 3;
        *(uint4*)(Og + (size_t)d * 512 + q8) = *(const uint4*)(Qs + d * 72 + q8);
    }
}

// ---------------- warp-per-row LayerNorm over E=512 ---------------------------
// 256 thr = 8 warps = 8 rows per block; each lane: 4 float4 (MLP 4), shuffle-only.
__global__ __launch_bounds__(256)
void ln_kernel(const float* __restrict__ in, const float* __restrict__ gw,
               const float* __restrict__ bw, float* __restrict__ out,
               __half* __restrict__ outh)
{
    int row = blockIdx.x * 8 + (threadIdx.x >> 5);
    int lane = threadIdx.x & 31;
    int s = row >> 11;

    const float* rp = in + (size_t)row * 512;
    float4 xv[4];
    #pragma unroll
    for (int i = 0; i < 4; ++i)
        xv[i] = *(const float4*)(rp + (lane + i * 32) * 4);

    float sum = 0.f, sq = 0.f;
    #pragma unroll
    for (int i = 0; i < 4; ++i) {
        sum += xv[i].x + xv[i].y + xv[i].z + xv[i].w;
        sq  += xv[i].x * xv[i].x + xv[i].y * xv[i].y
             + xv[i].z * xv[i].z + xv[i].w * xv[i].w;
    }
    #pragma unroll
    for (int off = 16; off >= 1; off >>= 1) {
        sum += __shfl_xor_sync(0xffffffffu, sum, off);
        sq  += __shfl_xor_sync(0xffffffffu, sq,  off);
    }

    float mean = sum * (1.0f / 512.0f);
    float var  = sq  * (1.0f / 512.0f) - mean * mean;
    float inv  = rsqrtf(var + 1e-5f);

    const float* gp = gw + s * 512;
    const float* bp = bw + s * 512;
    float* op = out + (size_t)row * 512;
    __half* ohp = outh ? outh + (size_t)row * 512 : nullptr;
    #pragma unroll
    for (int i = 0; i < 4; ++i) {
        int c = (lane + i * 32) * 4;
        float4 g4 = *(const float4*)(gp + c);
        float4 b4 = *(const float4*)(bp + c);
        float4 o;
        o.x = (xv[i].x - mean) * inv * g4.x + b4.x;
        o.y = (xv[i].y - mean) * inv * g4.y + b4.y;
        o.z = (xv[i].z - mean) * inv * g4.z + b4.z;
        o.w = (xv[i].w - mean) * inv * g4.w + b4.w;
        *(float4*)(op + c) = o;
        if (ohp) {
            *(__half2*)(ohp + c)     = __floats2half2_rn(o.x, o.y);
            *(__half2*)(ohp + c + 2) = __floats2half2_rn(o.z, o.w);
        }
    }
}

// ---------------- launch --------------------------------------------------------
extern "C" void kernel_launch(void* const* d_in, const int* in_sizes, int n_in,
                              void* d_out, int out_size)
{
    const float* xs0 = (const float*)d_in[0];
    const float* xs1 = (const float*)d_in[1];
    const float* xs2 = (const float*)d_in[2];
    const float* xs3 = (const float*)d_in[3];
    const float* Wq  = (const float*)d_in[4];
    const float* Wk  = (const float*)d_in[5];
    const float* Wv  = (const float*)d_in[6];
    const float* Wo  = (const float*)d_in[7];
    const float* bo  = (const float*)d_in[8];
    const float* ln1g = (const float*)d_in[9];
    const float* ln1b = (const float*)d_in[10];
    const float* ln2g = (const float*)d_in[11];
    const float* ln2b = (const float*)d_in[12];
    const float* W1  = (const float*)d_in[13];
    const float* bf1 = (const float*)d_in[14];
    const float* W2  = (const float*)d_in[15];
    const float* bf2 = (const float*)d_in[16];
    const float* inter = (const float*)d_in[17];

    __half *wqh, *wkh, *wvh, *woh, *w1h, *w2h, *xh, *mh, *hb, *r1h;
    float *t1, *r1, *t2;
    cudaGetSymbolAddress((void**)&wqh, g_Wqh);
    cudaGetSymbolAddress((void**)&wkh, g_Wkh);
    cudaGetSymbolAddress((void**)&wvh, g_Wvh);
    cudaGetSymbolAddress((void**)&woh, g_Woh);
    cudaGetSymbolAddress((void**)&w1h, g_W1h);
    cudaGetSymbolAddress((void**)&w2h, g_W2h);
    cudaGetSymbolAddress((void**)&xh,  g_Xh);
    cudaGetSymbolAddress((void**)&mh,  g_MH);
    cudaGetSymbolAddress((void**)&hb,  g_HB);
    cudaGetSymbolAddress((void**)&r1h, g_R1h);
    cudaGetSymbolAddress((void**)&t1,  g_T1);
    cudaGetSymbolAddress((void**)&r1,  g_R1);
    cudaGetSymbolAddress((void**)&t2,  g_T2);

    // fused conversion: 10 segments, 4096 elems per block
    CvtDesc cd;
    const int SW = 256;             // blocks per 512x512x4 weight / per x stream
    const int BW = 1024;            // blocks per 512x2048x4 weight
    cd.src[0] = Wq;  cd.dst[0] = wqh;
    cd.src[1] = Wk;  cd.dst[1] = wkh;
    cd.src[2] = Wv;  cd.dst[2] = wvh;
    cd.src[3] = Wo;  cd.dst[3] = woh;
    cd.src[4] = W1;  cd.dst[4] = w1h;
    cd.src[5] = W2;  cd.dst[5] = w2h;
    cd.src[6] = xs0; cd.dst[6] = xh;
    cd.src[7] = xs1; cd.dst[7] = xh + 1 * (size_t)MROWS * EMB;
    cd.src[8] = xs2; cd.dst[8] = xh + 2 * (size_t)MROWS * EMB;
    cd.src[9] = xs3; cd.dst[9] = xh + 3 * (size_t)MROWS * EMB;
    cd.start[0] = 0;
    cd.start[1] = SW;     cd.start[2] = 2 * SW;  cd.start[3] = 3 * SW;
    cd.start[4] = 4 * SW; cd.start[5] = 4 * SW + BW;
    cd.start[6] = 4 * SW + 2 * BW;
    cd.start[7] = cd.start[6] + SW;
    cd.start[8] = cd.start[7] + SW;
    cd.start[9] = cd.start[8] + SW;
    cd.start[10] = cd.start[9] + SW;   // 4096

    cvt_all<<<cd.start[10], 256>>>(cd);

    // QKV projections
    qkv_mma<<<dim3(4, 16, 12), 256>>>();

    // cross-stream attention
    attn_h<<<dim3(8, 8, 16), 128>>>(inter);

    // T1 = MH @ Wo + bo + x   (64-row tiles: short-K single-wave case)
    R4 rx; rx.p[0] = xs0; rx.p[1] = xs1; rx.p[2] = xs2; rx.p[3] = xs3;
    gemm_bias_resid64<<<dim3(4, 32, 4), 256>>>(mh, woh, bo, rx, t1, MROWS, EMB, EMB);

    // R1 = LN1(T1)  (fp32 + fp16 copies; warp-per-row)
    ln_kernel<<<1024, 256>>>(t1, ln1g, ln1b, r1, r1h);

    // HB = gelu(R1h @ W1 + bf1)
    gemm_bias_gelu<<<dim3(16, 16, 4), 256>>>(r1h, w1h, bf1, hb, MROWS, 4 * EMB, EMB);

    // T2 = HB @ W2 + bf2 + R1  (128-row tiles: long-K case)
    R4 rr; for (int s = 0; s < 4; ++s) rr.p[s] = r1 + (size_t)s * MROWS * EMB;
    gemm_bias_resid<<<dim3(4, 16, 4), 256>>>(hb, w2h, bf2, rr, t2, MROWS, EMB, 2048);

    // out = LN2(T2)
    ln_kernel<<<1024, 256>>>(t2, ln2g, ln2b, (float*)d_out, nullptr);
}

// round 14
// speedup vs baseline: 1.0432x; 1.0003x over previous
#include <cuda_runtime.h>
#include <cuda_fp16.h>
#include <math.h>
#include <stdint.h>

#define MROWS 2048
#define EMB   512

// ---------------- scratch (device globals) -----------------------------------
__device__ float  g_T1 [4UL*2048*512];
__device__ float  g_R1 [4UL*2048*512];
__device__ float  g_T2 [4UL*2048*512];
__device__ __half g_Xh [4UL*2048*512];
__device__ __half g_Q  [4UL*2048*512];   // [s,b,h,t,d]
__device__ __half g_K  [4UL*2048*512];
__device__ __half g_V  [4UL*2048*512];
__device__ __half g_MH [4UL*2048*512];   // pre-transposed attention out
__device__ __half g_R1h[4UL*2048*512];
__device__ __half g_HB [4UL*2048*2048];
__device__ __half g_Wqh[4UL*512*512];
__device__ __half g_Wkh[4UL*512*512];
__device__ __half g_Wvh[4UL*512*512];
__device__ __half g_Woh[4UL*512*512];
__device__ __half g_W1h[4UL*512*2048];
__device__ __half g_W2h[4UL*2048*512];

struct R4 { const float* p[4]; };
struct CvtDesc {
    const float* src[10];
    __half* dst[10];
    int start[11];
};

__device__ __forceinline__ float gelu_exact(float x) {
    return 0.5f * x * (1.0f + erff(x * 0.70710678118654752440f));
}
__device__ __forceinline__ uint32_t sptr(const void* p) {
    return (uint32_t)__cvta_generic_to_shared(p);
}
__device__ __forceinline__ void cpa16(void* s, const void* g) {
    asm volatile("cp.async.cg.shared.global [%0],[%1],16;\n" :: "r"(sptr(s)), "l"(g));
}
__device__ __forceinline__ void ldsm4(uint32_t& r0, uint32_t& r1, uint32_t& r2,
                                      uint32_t& r3, uint32_t a) {
    asm volatile("ldmatrix.sync.aligned.m8n8.x4.shared.b16 {%0,%1,%2,%3},[%4];\n"
        : "=r"(r0), "=r"(r1), "=r"(r2), "=r"(r3) : "r"(a));
}
__device__ __forceinline__ void ldsm4t(uint32_t& r0, uint32_t& r1, uint32_t& r2,
                                       uint32_t& r3, uint32_t a) {
    asm volatile("ldmatrix.sync.aligned.m8n8.x4.trans.shared.b16 {%0,%1,%2,%3},[%4];\n"
        : "=r"(r0), "=r"(r1), "=r"(r2), "=r"(r3) : "r"(a));
}
__device__ __forceinline__ void mmaf16(float& d0, float& d1, float& d2, float& d3,
    uint32_t a0, uint32_t a1, uint32_t a2, uint32_t a3, uint32_t b0, uint32_t b1) {
    asm volatile("mma.sync.aligned.m16n8k16.row.col.f32.f16.f16.f32 "
        "{%0,%1,%2,%3},{%4,%5,%6,%7},{%8,%9},{%0,%1,%2,%3};\n"
        : "+f"(d0), "+f"(d1), "+f"(d2), "+f"(d3)
        : "r"(a0), "r"(a1), "r"(a2), "r"(a3), "r"(b0), "r"(b1));
}
__device__ __forceinline__ uint32_t packh2(float x, float y) {
    __half2 h = __floats2half2_rn(x, y);
    return *(uint32_t*)&h;
}
__device__ __forceinline__ float ex2f(float x) {
    float y; asm("ex2.approx.f32 %0, %1;" : "=f"(y) : "f"(x)); return y;
}

// ---------------- fused fp32->fp16 converter (4 float4 per thread) -------------
__global__ __launch_bounds__(256)
void cvt_all(CvtDesc d)
{
    int b = blockIdx.x;
    int seg = 0;
    #pragma unroll
    for (int k = 0; k < 9; ++k)
        if (b >= d.start[seg + 1]) ++seg;
    int base = (b - d.start[seg]) * 4096 + threadIdx.x * 4;
    const float* s = d.src[seg];
    __half* o = d.dst[seg];
    float4 v[4];
    #pragma unroll
    for (int i = 0; i < 4; ++i)
        v[i] = *(const float4*)(s + base + i * 1024);
    #pragma unroll
    for (int i = 0; i < 4; ++i) {
        int off = base + i * 1024;
        *(__half2*)(o + off)     = __floats2half2_rn(v[i].x, v[i].y);
        *(__half2*)(o + off + 2) = __floats2half2_rn(v[i].z, v[i].w);
    }
}

// ---------------- fp16 MMA GEMM core: 128x128x32, 256 thr, 2-stage -------------
#define LDA 40
#define LDB 152
#define AS_SZ (128*LDA)
#define BS_SZ (32*LDB)

__device__ __forceinline__ void stage_h(const __half* Ag, const __half* Bg,
    int K, int N, __half* Ad, __half* Bd, int tid)
{
    #pragma unroll
    for (int i = 0; i < 2; ++i) {
        int c = tid + (i << 8);
        int ar = c >> 2, ac = (c & 3) << 3;
        cpa16(Ad + ar * LDA + ac, Ag + (size_t)ar * K + ac);
        int br = c >> 4, bn = (c & 15) << 3;
        cpa16(Bd + br * LDB + bn, Bg + (size_t)br * N + bn);
    }
    asm volatile("cp.async.commit_group;\n" ::: "memory");
}

__device__ __forceinline__ void mainloop_h(
    const __half* __restrict__ A, const __half* __restrict__ B,
    int K, int N, int m0, int n0, float (&acc)[4][4][4],
    __half* As, __half* Bs)
{
    const int tid = threadIdx.x, lane = tid & 31, warp = tid >> 5;
    const int wm = (warp & 1) * 64, wn = (warp >> 1) * 32;
    const int KT = K >> 5;
    const int lrow = lane & 15, lsel = (lane >> 4) << 3;

    stage_h(A + (size_t)m0 * K, B + n0, K, N, As, Bs, tid);

    for (int kt = 0; kt < KT; ++kt) {
        int buf = kt & 1;
        if (kt + 1 < KT) {
            stage_h(A + (size_t)m0 * K + (kt + 1) * 32,
                    B + (size_t)(kt + 1) * 32 * N + n0, K, N,
                    As + (buf ^ 1) * AS_SZ, Bs + (buf ^ 1) * BS_SZ, tid);
            asm volatile("cp.async.wait_group 1;\n" ::: "memory");
        } else {
            asm volatile("cp.async.wait_group 0;\n" ::: "memory");
        }
        __syncthreads();
        const __half* Ad = As + buf * AS_SZ;
        const __half* Bd = Bs + buf * BS_SZ;
        #pragma unroll
        for (int kk = 0; kk < 2; ++kk) {
            int kb = kk * 16;
            uint32_t af[4][4], bf[2][4];
            #pragma unroll
            for (int mi = 0; mi < 4; ++mi)
                ldsm4(af[mi][0], af[mi][1], af[mi][2], af[mi][3],
                      sptr(Ad + (wm + mi * 16 + lrow) * LDA + kb + lsel));
            #pragma unroll
            for (int p = 0; p < 2; ++p)
                ldsm4t(bf[p][0], bf[p][1], bf[p][2], bf[p][3],
                       sptr(Bd + (kb + lrow) * LDB + wn + p * 16 + lsel));
            #pragma unroll
            for (int mi = 0; mi < 4; ++mi)
                #pragma unroll
                for (int ni = 0; ni < 4; ++ni)
                    mmaf16(acc[mi][ni][0], acc[mi][ni][1], acc[mi][ni][2], acc[mi][ni][3],
                           af[mi][0], af[mi][1], af[mi][2], af[mi][3],
                           bf[ni >> 1][(ni & 1) * 2], bf[ni >> 1][(ni & 1) * 2 + 1]);
        }
        __syncthreads();
    }
}

// ---------------- 64x64 variant, 128 thr (small-GEMM wave booster: Wo) ---------
#define LDB64 72
#define AS64 (64*LDA)
#define BS64 (32*LDB64)

__device__ __forceinline__ void stage_w(const __half* Ag, const __half* Bg,
    int K, int N, __half* Ad, __half* Bd, int tid)
{
    #pragma unroll
    for (int i = 0; i < 2; ++i) {
        int c = tid + (i << 7);
        int ar = c >> 2, ac = (c & 3) << 3;
        cpa16(Ad + ar * LDA + ac, Ag + (size_t)ar * K + ac);
        int br = c >> 3, bn = (c & 7) << 3;
        cpa16(Bd + br * LDB64 + bn, Bg + (size_t)br * N + bn);
    }
    asm volatile("cp.async.commit_group;\n" ::: "memory");
}

__device__ __forceinline__ void mainloop_w(
    const __half* __restrict__ A, const __half* __restrict__ B,
    int K, int N, int m0, int n0, float (&acc)[2][4][4],
    __half* As, __half* Bs)
{
    const int tid = threadIdx.x, lane = tid & 31, warp = tid >> 5;
    const int wm = (warp & 1) * 32, wn = (warp >> 1) * 32;
    const int KT = K >> 5;
    const int lrow = lane & 15, lsel = (lane >> 4) << 3;

    stage_w(A + (size_t)m0 * K, B + n0, K, N, As, Bs, tid);

    for (int kt = 0; kt < KT; ++kt) {
        int buf = kt & 1;
        if (kt + 1 < KT) {
            stage_w(A + (size_t)m0 * K + (kt + 1) * 32,
                    B + (size_t)(kt + 1) * 32 * N + n0, K, N,
                    As + (buf ^ 1) * AS64, Bs + (buf ^ 1) * BS64, tid);
            asm volatile("cp.async.wait_group 1;\n" ::: "memory");
        } else {
            asm volatile("cp.async.wait_group 0;\n" ::: "memory");
        }
        __syncthreads();
        const __half* Ad = As + buf * AS64;
        const __half* Bd = Bs + buf * BS64;
        #pragma unroll
        for (int kk = 0; kk < 2; ++kk) {
            int kb = kk * 16;
            uint32_t af[2][4], bf[2][4];
            #pragma unroll
            for (int mi = 0; mi < 2; ++mi)
                ldsm4(af[mi][0], af[mi][1], af[mi][2], af[mi][3],
                      sptr(Ad + (wm + mi * 16 + lrow) * LDA + kb + lsel));
            #pragma unroll
            for (int p = 0; p < 2; ++p)
                ldsm4t(bf[p][0], bf[p][1], bf[p][2], bf[p][3],
                       sptr(Bd + (kb + lrow) * LDB64 + wn + p * 16 + lsel));
            #pragma unroll
            for (int mi = 0; mi < 2; ++mi)
                #pragma unroll
                for (int ni = 0; ni < 4; ++ni)
                    mmaf16(acc[mi][ni][0], acc[mi][ni][1], acc[mi][ni][2], acc[mi][ni][3],
                           af[mi][0], af[mi][1], af[mi][2], af[mi][3],
                           bf[ni >> 1][(ni & 1) * 2], bf[ni >> 1][(ni & 1) * 2 + 1]);
        }
        __syncthreads();
    }
}

// ---------------- QKV: Xh @ W -> scatter half [s,b,h,t,d] --------------------
__global__ __launch_bounds__(256)
void qkv_mma()
{
    __shared__ __half As[2 * AS_SZ];
    __shared__ __half Bs[2 * BS_SZ];
    int z = blockIdx.z; int s = z / 3, p = z - 3 * s;
    const __half* A = g_Xh + (size_t)s * MROWS * EMB;
    const __half* W = (p == 0 ? g_Wqh : (p == 1 ? g_Wkh : g_Wvh)) + (size_t)s * EMB * EMB;
    __half* O = (p == 0 ? g_Q : (p == 1 ? g_K : g_V));
    int m0 = blockIdx.y * 128, n0 = blockIdx.x * 128;

    float acc[4][4][4] = {};
    mainloop_h(A, W, EMB, EMB, m0, n0, acc, As, Bs);

    const int lane = threadIdx.x & 31, warp = threadIdx.x >> 5;
    const int wm = (warp & 1) * 64, wn = (warp >> 1) * 32;
    const int gg = lane >> 2, rr = lane & 3;
    #pragma unroll
    for (int mi = 0; mi < 4; ++mi) {
        int r0 = m0 + wm + mi * 16 + gg;
        #pragma unroll
        for (int ni = 0; ni < 4; ++ni) {
            int c = n0 + wn + ni * 8 + rr * 2;
            int hh = c >> 6, d = c & 63;
            #pragma unroll
            for (int hr = 0; hr < 2; ++hr) {
                int rw = r0 + hr * 8;
                int b = rw >> 9, t = rw & 511;
                size_t dst = ((((size_t)s * 4 + b) * 8 + hh) * 512 + t) * 64 + d;
                __half2 hv = __floats2half2_rn(acc[mi][ni][hr * 2], acc[mi][ni][hr * 2 + 1]);
                *(__half2*)(O + dst) = hv;
            }
        }
    }
}

// ---------------- 64x64 GEMM + bias + resid -> fp32 (Wo) -----------------------
__global__ __launch_bounds__(128)
void gemm_wo(const __half* __restrict__ Ab, const __half* __restrict__ Bb,
             const float* __restrict__ biasb, R4 resid,
             float* __restrict__ Cb, int M, int N, int K)
{
    __shared__ __half As[2 * AS64];
    __shared__ __half Bs[2 * BS64];
    int s = blockIdx.z;
    const __half* A = Ab + (size_t)s * M * K;
    const __half* B = Bb + (size_t)s * K * N;
    const float* bias = biasb + (size_t)s * N;
    const float* R = resid.p[s];
    float* C = Cb + (size_t)s * M * N;
    int m0 = blockIdx.y * 64, n0 = blockIdx.x * 64;

    float acc[2][4][4] = {};
    mainloop_w(A, B, K, N, m0, n0, acc, As, Bs);

    const int lane = threadIdx.x & 31, warp = threadIdx.x >> 5;
    const int wm = (warp & 1) * 32, wn = (warp >> 1) * 32;
    const int gg = lane >> 2, rr = lane & 3;
    #pragma unroll
    for (int mi = 0; mi < 2; ++mi) {
        int r0 = m0 + wm + mi * 16 + gg;
        #pragma unroll
        for (int ni = 0; ni < 4; ++ni) {
            int c = n0 + wn + ni * 8 + rr * 2;
            float bx = bias[c], by = bias[c + 1];
            #pragma unroll
            for (int hr = 0; hr < 2; ++hr) {
                int rw = r0 + hr * 8;
                float2 rv = *(const float2*)(R + (size_t)rw * N + c);
                float v0 = acc[mi][ni][hr * 2 + 0] + bx + rv.x;
                float v1 = acc[mi][ni][hr * 2 + 1] + by + rv.y;
                *(float2*)(C + (size_t)rw * N + c) = make_float2(v0, v1);
            }
        }
    }
}

// ---------------- 128-tile GEMM + bias + resid -> fp32 (FFN2) ------------------
__global__ __launch_bounds__(256)
void gemm_bias_resid(const __half* __restrict__ Ab, const __half* __restrict__ Bb,
                     const float* __restrict__ biasb, R4 resid,
                     float* __restrict__ Cb, int M, int N, int K)
{
    __shared__ __half As[2 * AS_SZ];
    __shared__ __half Bs[2 * BS_SZ];
    int s = blockIdx.z;
    const __half* A = Ab + (size_t)s * M * K;
    const __half* B = Bb + (size_t)s * K * N;
    const float* bias = biasb + (size_t)s * N;
    const float* R = resid.p[s];
    float* C = Cb + (size_t)s * M * N;
    int m0 = blockIdx.y * 128, n0 = blockIdx.x * 128;

    float acc[4][4][4] = {};
    mainloop_h(A, B, K, N, m0, n0, acc, As, Bs);

    const int lane = threadIdx.x & 31, warp = threadIdx.x >> 5;
    const int wm = (warp & 1) * 64, wn = (warp >> 1) * 32;
    const int gg = lane >> 2, rr = lane & 3;
    #pragma unroll
    for (int mi = 0; mi < 4; ++mi) {
        int r0 = m0 + wm + mi * 16 + gg;
        #pragma unroll
        for (int ni = 0; ni < 4; ++ni) {
            int c = n0 + wn + ni * 8 + rr * 2;
            float bx = bias[c], by = bias[c + 1];
            #pragma unroll
            for (int hr = 0; hr < 2; ++hr) {
                int rw = r0 + hr * 8;
                float2 rv = *(const float2*)(R + (size_t)rw * N + c);
                float v0 = acc[mi][ni][hr * 2 + 0] + bx + rv.x;
                float v1 = acc[mi][ni][hr * 2 + 1] + by + rv.y;
                *(float2*)(C + (size_t)rw * N + c) = make_float2(v0, v1);
            }
        }
    }
}

// ---------------- GEMM + bias + gelu -> fp16 (FFN1) ----------------------------
__global__ __launch_bounds__(256)
void gemm_bias_gelu(const __half* __restrict__ Ab, const __half* __restrict__ Bb,
                    const float* __restrict__ biasb, __half* __restrict__ Cb,
                    int M, int N, int K)
{
    __shared__ __half As[2 * AS_SZ];
    __shared__ __half Bs[2 * BS_SZ];
    int s = blockIdx.z;
    const __half* A = Ab + (size_t)s * M * K;
    const __half* B = Bb + (size_t)s * K * N;
    const float* bias = biasb + (size_t)s * N;
    __half* C = Cb + (size_t)s * M * N;
    int m0 = blockIdx.y * 128, n0 = blockIdx.x * 128;

    float acc[4][4][4] = {};
    mainloop_h(A, B, K, N, m0, n0, acc, As, Bs);

    const int lane = threadIdx.x & 31, warp = threadIdx.x >> 5;
    const int wm = (warp & 1) * 64, wn = (warp >> 1) * 32;
    const int gg = lane >> 2, rr = lane & 3;
    #pragma unroll
    for (int mi = 0; mi < 4; ++mi) {
        int r0 = m0 + wm + mi * 16 + gg;
        #pragma unroll
        for (int ni = 0; ni < 4; ++ni) {
            int c = n0 + wn + ni * 8 + rr * 2;
            float bx = bias[c], by = bias[c + 1];
            #pragma unroll
            for (int hr = 0; hr < 2; ++hr) {
                int rw = r0 + hr * 8;
                float v0 = gelu_exact(acc[mi][ni][hr * 2 + 0] + bx);
                float v1 = gelu_exact(acc[mi][ni][hr * 2 + 1] + by);
                *(__half2*)(C + (size_t)rw * N + c) = __floats2half2_rn(v0, v1);
            }
        }
    }
}

// ---------------- cross-stream flash attention (serial KV, no-max softmax) -----
__global__ __launch_bounds__(128)
void attn_h(const float* __restrict__ inter)
{
    __shared__ __half Qs[64 * 72];
    __shared__ __half Ks[64 * 72];
    __shared__ __half Vs[64 * 72];

    const int tid = threadIdx.x, lane = tid & 31, warp = tid >> 5;
    const int qt = blockIdx.x, h = blockIdx.y, ib = blockIdx.z;
    const int i = ib >> 2, b = ib & 3;
    const int gg = lane >> 2, rr = lane & 3;
    const int lrow = lane & 15, lsel = (lane >> 4) << 3;

    const __half* Qg = g_Q + ((((size_t)i * 4 + b) * 8 + h) * 512 + qt * 64) * 64;
    #pragma unroll
    for (int it = 0; it < 4; ++it) {
        int c = tid + it * 128;
        int q = c >> 3, d8 = (c & 7) << 3;
        cpa16(Qs + q * 72 + d8, Qg + q * 64 + d8);
    }
    asm volatile("cp.async.commit_group;\ncp.async.wait_group 0;\n" ::: "memory");
    __syncthreads();

    uint32_t qf[4][4];
    #pragma unroll
    for (int kf = 0; kf < 4; ++kf)
        ldsm4(qf[kf][0], qf[kf][1], qf[kf][2], qf[kf][3],
              sptr(Qs + (warp * 16 + lrow) * 72 + kf * 16 + lsel));

    float Of[8][4] = {};
    for (int j = 0; j < 4; ++j) {
        float cj2 = 0.125f * 1.44269504f * __ldg(inter + i * 4 + j);
        const __half* Kg = g_K + (((size_t)j * 4 + b) * 8 + h) * 512 * 64;
        const __half* Vg = g_V + (((size_t)j * 4 + b) * 8 + h) * 512 * 64;
        float l0 = 0.f, l1 = 0.f;
        float Oj[8][4] = {};

        for (int kt = 0; kt < 8; ++kt) {
            __syncthreads();
            #pragma unroll
            for (int it = 0; it < 4; ++it) {
                int c = tid + it * 128;
                int r = c >> 3, d8 = (c & 7) << 3;
                cpa16(Ks + r * 72 + d8, Kg + (size_t)(kt * 64 + r) * 64 + d8);
                cpa16(Vs + r * 72 + d8, Vg + (size_t)(kt * 64 + r) * 64 + d8);
            }
            asm volatile("cp.async.commit_group;\ncp.async.wait_group 0;\n" ::: "memory");
            __syncthreads();

            float S[8][4] = {};
            #pragma unroll
            for (int nf = 0; nf < 8; ++nf) {
                uint32_t kb[2][4];
                #pragma unroll
                for (int p = 0; p < 2; ++p)
                    ldsm4(kb[p][0], kb[p][1], kb[p][2], kb[p][3],
                          sptr(Ks + (nf * 8 + (lane & 7)) * 72 + p * 32 + ((lane >> 3) << 3)));
                #pragma unroll
                for (int kf = 0; kf < 4; ++kf)
                    mmaf16(S[nf][0], S[nf][1], S[nf][2], S[nf][3],
                           qf[kf][0], qf[kf][1], qf[kf][2], qf[kf][3],
                           kb[kf >> 1][(kf & 1) * 2], kb[kf >> 1][(kf & 1) * 2 + 1]);
            }

            uint32_t pf[4][4];
            #pragma unroll
            for (int nf = 0; nf < 8; ++nf) {
                float p0 = ex2f(S[nf][0] * cj2), p1 = ex2f(S[nf][1] * cj2);
                float p2 = ex2f(S[nf][2] * cj2), p3 = ex2f(S[nf][3] * cj2);
                l0 += p0 + p1; l1 += p2 + p3;
                int kf = nf >> 1;
                if ((nf & 1) == 0) { pf[kf][0] = packh2(p0, p1); pf[kf][1] = packh2(p2, p3); }
                else               { pf[kf][2] = packh2(p0, p1); pf[kf][3] = packh2(p2, p3); }
            }

            #pragma unroll
            for (int kf = 0; kf < 4; ++kf) {
                #pragma unroll
                for (int p = 0; p < 4; ++p) {
                    uint32_t vb[4];
                    ldsm4t(vb[0], vb[1], vb[2], vb[3],
                           sptr(Vs + (kf * 16 + lrow) * 72 + p * 16 + lsel));
                    mmaf16(Oj[2 * p][0], Oj[2 * p][1], Oj[2 * p][2], Oj[2 * p][3],
                           pf[kf][0], pf[kf][1], pf[kf][2], pf[kf][3], vb[0], vb[1]);
                    mmaf16(Oj[2 * p + 1][0], Oj[2 * p + 1][1], Oj[2 * p + 1][2], Oj[2 * p + 1][3],
                           pf[kf][0], pf[kf][1], pf[kf][2], pf[kf][3], vb[2], vb[3]);
                }
            }
        }
        l0 += __shfl_xor_sync(0xffffffffu, l0, 1);
        l0 += __shfl_xor_sync(0xffffffffu, l0, 2);
        l1 += __shfl_xor_sync(0xffffffffu, l1, 1);
        l1 += __shfl_xor_sync(0xffffffffu, l1, 2);
        float inv0 = 0.25f / l0, inv1 = 0.25f / l1;
        #pragma unroll
        for (int nf = 0; nf < 8; ++nf) {
            Of[nf][0] += Oj[nf][0] * inv0; Of[nf][1] += Oj[nf][1] * inv0;
            Of[nf][2] += Oj[nf][2] * inv1; Of[nf][3] += Oj[nf][3] * inv1;
        }
    }

    __syncthreads();
    #pragma unroll
    for (int nf = 0; nf < 8; ++nf) {
        int col = nf * 8 + rr * 2;
        int lq = warp * 16 + gg;
        Qs[col * 72 + lq]           = __float2half(Of[nf][0]);
        Qs[(col + 1) * 72 + lq]     = __float2half(Of[nf][1]);
        Qs[col * 72 + lq + 8]       = __float2half(Of[nf][2]);
        Qs[(col + 1) * 72 + lq + 8] = __float2half(Of[nf][3]);
    }
    __syncthreads();
    __half* Og = g_MH + (((size_t)i * 4 + b) * 512 + h * 64) * 512 + qt * 64;
    #pragma unroll
    for (int it = 0; it < 4; ++it) {
        int c = tid + it * 128;
        int d = c >> 3, q8 = (c & 7) << 3;
        *(uint4*)(Og + (size_t)d * 512 + q8) = *(const uint4*)(Qs + d * 72 + q8);
    }
}

// ---------------- warp-per-row LayerNorm over E=512 ---------------------------
__global__ __launch_bounds__(256)
void ln_kernel(const float* __restrict__ in, const float* __restrict__ gw,
               const float* __restrict__ bw, float* __restrict__ out,
               __half* __restrict__ outh)
{
    int row = blockIdx.x * 8 + (threadIdx.x >> 5);
    int lane = threadIdx.x & 31;
    int s = row >> 11;

    const float* rp = in + (size_t)row * 512;
    float4 xv[4];
    #pragma unroll
    for (int i = 0; i < 4; ++i)
        xv[i] = *(const float4*)(rp + (lane + i * 32) * 4);

    float sum = 0.f, sq = 0.f;
    #pragma unroll
    for (int i = 0; i < 4; ++i) {
        sum += xv[i].x + xv[i].y + xv[i].z + xv[i].w;
        sq  += xv[i].x * xv[i].x + xv[i].y * xv[i].y
             + xv[i].z * xv[i].z + xv[i].w * xv[i].w;
    }
    #pragma unroll
    for (int off = 16; off >= 1; off >>= 1) {
        sum += __shfl_xor_sync(0xffffffffu, sum, off);
        sq  += __shfl_xor_sync(0xffffffffu, sq,  off);
    }

    float mean = sum * (1.0f / 512.0f);
    float var  = sq  * (1.0f / 512.0f) - mean * mean;
    float inv  = rsqrtf(var + 1e-5f);

    const float* gp = gw + s * 512;
    const float* bp = bw + s * 512;
    float* op = out + (size_t)row * 512;
    __half* ohp = outh ? outh + (size_t)row * 512 : nullptr;
    #pragma unroll
    for (int i = 0; i < 4; ++i) {
        int c = (lane + i * 32) * 4;
        float4 g4 = *(const float4*)(gp + c);
        float4 b4 = *(const float4*)(bp + c);
        float4 o;
        o.x = (xv[i].x - mean) * inv * g4.x + b4.x;
        o.y = (xv[i].y - mean) * inv * g4.y + b4.y;
        o.z = (xv[i].z - mean) * inv * g4.z + b4.z;
        o.w = (xv[i].w - mean) * inv * g4.w + b4.w;
        *(float4*)(op + c) = o;
        if (ohp) {
            *(__half2*)(ohp + c)     = __floats2half2_rn(o.x, o.y);
            *(__half2*)(ohp + c + 2) = __floats2half2_rn(o.z, o.w);
        }
    }
}

// ---------------- launch --------------------------------------------------------
extern "C" void kernel_launch(void* const* d_in, const int* in_sizes, int n_in,
                              void* d_out, int out_size)
{
    const float* xs0 = (const float*)d_in[0];
    const float* xs1 = (const float*)d_in[1];
    const float* xs2 = (const float*)d_in[2];
    const float* xs3 = (const float*)d_in[3];
    const float* Wq  = (const float*)d_in[4];
    const float* Wk  = (const float*)d_in[5];
    const float* Wv  = (const float*)d_in[6];
    const float* Wo  = (const float*)d_in[7];
    const float* bo  = (const float*)d_in[8];
    const float* ln1g = (const float*)d_in[9];
    const float* ln1b = (const float*)d_in[10];
    const float* ln2g = (const float*)d_in[11];
    const float* ln2b = (const float*)d_in[12];
    const float* W1  = (const float*)d_in[13];
    const float* bf1 = (const float*)d_in[14];
    const float* W2  = (const float*)d_in[15];
    const float* bf2 = (const float*)d_in[16];
    const float* inter = (const float*)d_in[17];

    __half *wqh, *wkh, *wvh, *woh, *w1h, *w2h, *xh, *mh, *hb, *r1h;
    float *t1, *r1, *t2;
    cudaGetSymbolAddress((void**)&wqh, g_Wqh);
    cudaGetSymbolAddress((void**)&wkh, g_Wkh);
    cudaGetSymbolAddress((void**)&wvh, g_Wvh);
    cudaGetSymbolAddress((void**)&woh, g_Woh);
    cudaGetSymbolAddress((void**)&w1h, g_W1h);
    cudaGetSymbolAddress((void**)&w2h, g_W2h);
    cudaGetSymbolAddress((void**)&xh,  g_Xh);
    cudaGetSymbolAddress((void**)&mh,  g_MH);
    cudaGetSymbolAddress((void**)&hb,  g_HB);
    cudaGetSymbolAddress((void**)&r1h, g_R1h);
    cudaGetSymbolAddress((void**)&t1,  g_T1);
    cudaGetSymbolAddress((void**)&r1,  g_R1);
    cudaGetSymbolAddress((void**)&t2,  g_T2);

    // fused conversion: 10 segments, 4096 elems per block
    CvtDesc cd;
    const int SW = 256;
    const int BW = 1024;
    cd.src[0] = Wq;  cd.dst[0] = wqh;
    cd.src[1] = Wk;  cd.dst[1] = wkh;
    cd.src[2] = Wv;  cd.dst[2] = wvh;
    cd.src[3] = Wo;  cd.dst[3] = woh;
    cd.src[4] = W1;  cd.dst[4] = w1h;
    cd.src[5] = W2;  cd.dst[5] = w2h;
    cd.src[6] = xs0; cd.dst[6] = xh;
    cd.src[7] = xs1; cd.dst[7] = xh + 1 * (size_t)MROWS * EMB;
    cd.src[8] = xs2; cd.dst[8] = xh + 2 * (size_t)MROWS * EMB;
    cd.src[9] = xs3; cd.dst[9] = xh + 3 * (size_t)MROWS * EMB;
    cd.start[0] = 0;
    cd.start[1] = SW;     cd.start[2] = 2 * SW;  cd.start[3] = 3 * SW;
    cd.start[4] = 4 * SW; cd.start[5] = 4 * SW + BW;
    cd.start[6] = 4 * SW + 2 * BW;
    cd.start[7] = cd.start[6] + SW;
    cd.start[8] = cd.start[7] + SW;
    cd.start[9] = cd.start[8] + SW;
    cd.start[10] = cd.start[9] + SW;   // 4096

    cvt_all<<<cd.start[10], 256>>>(cd);

    // QKV projections
    qkv_mma<<<dim3(4, 16, 12), 256>>>();

    // cross-stream attention
    attn_h<<<dim3(8, 8, 16), 128>>>(inter);

    // T1 = MH @ Wo + bo + x   (64x64 tiles -> 1024 CTAs, high occupancy)
    R4 rx; rx.p[0] = xs0; rx.p[1] = xs1; rx.p[2] = xs2; rx.p[3] = xs3;
    gemm_wo<<<dim3(8, 32, 4), 128>>>(mh, woh, bo, rx, t1, MROWS, EMB, EMB);

    // R1 = LN1(T1)  (fp32 + fp16 copies; warp-per-row)
    ln_kernel<<<1024, 256>>>(t1, ln1g, ln1b, r1, r1h);

    // HB = gelu(R1h @ W1 + bf1)
    gemm_bias_gelu<<<dim3(16, 16, 4), 256>>>(r1h, w1h, bf1, hb, MROWS, 4 * EMB, EMB);

    // T2 = HB @ W2 + bf2 + R1  (128-row tiles: long-K case)
    R4 rr; for (int s = 0; s < 4; ++s) rr.p[s] = r1 + (size_t)s * MROWS * EMB;
    gemm_bias_resid<<<dim3(4, 16, 4), 256>>>(hb, w2h, bf2, rr, t2, MROWS, EMB, 2048);

    // out = LN2(T2)
    ln_kernel<<<1024, 256>>>(t2, ln2g, ln2b, (float*)d_out, nullptr);
}